// round 8
// baseline (speedup 1.0000x reference)
#include <cuda_runtime.h>
#include <cstdint>
#include <math.h>

#define DI __device__ __forceinline__

constexpr int SEQ = 2048;
constexpr int DM  = 1024;
constexpr int NH  = 16;
constexpr int DK  = 64;
constexpr int RAD = 128;          // masksize // 2
constexpr int NBATCH = 2;
constexpr int NROW = NBATCH * SEQ;   // 4096 rows for all projections
constexpr int NZCTA = 256;           // zero-fill worker CTAs inside qkv launch

// ---------------- scratch (no allocation allowed) ----------------
__device__ __align__(256) float g_q[NBATCH * NH * SEQ * DK];
__device__ __align__(256) float g_k[NBATCH * NH * SEQ * DK];
__device__ __align__(256) float g_v[NBATCH * NH * SEQ * DK];
__device__ __align__(256) float g_x[NBATCH * SEQ * DM];

// ---------------- tf32 helpers ----------------
DI uint32_t f2tf32(float x) {
    uint32_t r;
    asm("cvt.rna.tf32.f32 %0, %1;" : "=r"(r) : "f"(x));
    return r;
}

DI void mma8(float* d, const uint32_t* a, const uint32_t* b) {
    asm volatile(
        "mma.sync.aligned.m16n8k8.row.col.f32.tf32.tf32.f32 "
        "{%0,%1,%2,%3}, {%4,%5,%6,%7}, {%8,%9}, {%0,%1,%2,%3};\n"
        : "+f"(d[0]), "+f"(d[1]), "+f"(d[2]), "+f"(d[3])
        : "r"(a[0]), "r"(a[1]), "r"(a[2]), "r"(a[3]),
          "r"(b[0]), "r"(b[1]));
}

// ---------------- zero-fill body (p outside the attention windows) -----
DI void zero_p_body(float4* __restrict__ p, int cta, int ncta) {
    const size_t total = (size_t)32 * SEQ * (SEQ / 4);   // 33.5M float4
    const float4 z = make_float4(0.f, 0.f, 0.f, 0.f);
    const size_t stride = (size_t)ncta * 256;
    for (size_t i = (size_t)cta * 256 + threadIdx.x; i < total; i += stride) {
        const int col = ((int)(i & 511)) << 2;          // 0..2044 step 4
        const int row = (int)((i >> 9) & (SEQ - 1));
        const int q0  = row & ~63;
        const int klo = max(0, q0 - RAD);
        const int khi = min(SEQ, q0 + 64 + RAD);
        if (col >= klo && col < khi) continue;          // attn writes the window
        __stcs(&p[i], z);
    }
}

// ======================================================================
// GEMM body: out = X[4096,1024] @ W[1024,1024] + bias
// BM=128, BN=64, BK=32, 256 threads (8 warps as 4x2), warp tile 32x32.
// acc = 32 regs/thread; __launch_bounds__(256,3) -> 3 CTAs/SM, 24 warps.
// mode 0: out[r*1024 + c]; mode 1: head-scatter to [B,H,S,dk]
// ======================================================================
constexpr int BS_STR = 72;   // mod 32 == 8 -> conflict-free B frags

DI void gemm_body(const float* __restrict__ X, const float* __restrict__ Wt,
                  const float* __restrict__ bias, float* __restrict__ out,
                  int mode, int bx, int by) {
    __shared__ uint32_t As[128 * 36];       // stride 36 (mod 32 == 4)
    __shared__ uint32_t Bs[32 * BS_STR];    // 32 k-rows x 64 cols

    const int tid  = threadIdx.x;
    const int lane = tid & 31;
    const int warp = tid >> 5;
    const int row0 = by * 128;
    const int col0 = bx * 64;
    const int wm = (warp >> 1) * 32;   // 0,32,64,96
    const int wn = (warp & 1) * 32;    // 0,32

    float acc[2][4][4];
#pragma unroll
    for (int i = 0; i < 2; i++)
#pragma unroll
        for (int j = 0; j < 4; j++)
#pragma unroll
            for (int e = 0; e < 4; e++) acc[i][j][e] = 0.f;

    const int ar = tid >> 3,  ac = (tid & 7) << 2;    // A: 32 rows/pass x 32 cols
    const int br = tid >> 4,  bc = (tid & 15) << 2;   // B: 16 rows/pass x 64 cols

    for (int kt = 0; kt < DM; kt += 32) {
#pragma unroll
        for (int i = 0; i < 4; i++) {
            const float4 v = *(const float4*)&X[(size_t)(row0 + ar + 32 * i) * DM + kt + ac];
            uint4 u;
            u.x = f2tf32(v.x); u.y = f2tf32(v.y); u.z = f2tf32(v.z); u.w = f2tf32(v.w);
            *(uint4*)&As[(ar + 32 * i) * 36 + ac] = u;
        }
#pragma unroll
        for (int i = 0; i < 2; i++) {
            const float4 v = *(const float4*)&Wt[(size_t)(kt + br + 16 * i) * DM + col0 + bc];
            uint4 u;
            u.x = f2tf32(v.x); u.y = f2tf32(v.y); u.z = f2tf32(v.z); u.w = f2tf32(v.w);
            *(uint4*)&Bs[(br + 16 * i) * BS_STR + bc] = u;
        }
        __syncthreads();

#pragma unroll
        for (int kk = 0; kk < 32; kk += 8) {
            uint32_t af[2][4], bf[4][2];
#pragma unroll
            for (int mt = 0; mt < 2; mt++) {
                const int r = wm + mt * 16 + (lane >> 2);
                const int c = kk + (lane & 3);
                af[mt][0] = As[r * 36 + c];
                af[mt][1] = As[(r + 8) * 36 + c];
                af[mt][2] = As[r * 36 + c + 4];
                af[mt][3] = As[(r + 8) * 36 + c + 4];
            }
#pragma unroll
            for (int nt = 0; nt < 4; nt++) {
                const int cB = wn + nt * 8 + (lane >> 2);
                const int rB = kk + (lane & 3);
                bf[nt][0] = Bs[rB * BS_STR + cB];
                bf[nt][1] = Bs[(rB + 4) * BS_STR + cB];
            }
#pragma unroll
            for (int mt = 0; mt < 2; mt++)
#pragma unroll
                for (int nt = 0; nt < 4; nt++) mma8(acc[mt][nt], af[mt], bf[nt]);
        }
        __syncthreads();
    }

    // epilogue
#pragma unroll
    for (int mt = 0; mt < 2; mt++)
#pragma unroll
        for (int nt = 0; nt < 4; nt++) {
            const int r0 = row0 + wm + mt * 16 + (lane >> 2);
            const int c0 = col0 + wn + nt * 8 + ((lane & 3) << 1);
#pragma unroll
            for (int e = 0; e < 4; e++) {
                const int r = r0 + ((e >> 1) << 3);
                const int c = c0 + (e & 1);
                const float v = acc[mt][nt][e] + bias[c];
                if (mode == 0) {
                    out[(size_t)r * DM + c] = v;
                } else {
                    const int b = r >> 11, s2 = r & (SEQ - 1);
                    const int h = c >> 6,  d = c & 63;
                    out[((((size_t)b * NH + h) * SEQ + s2) << 6) + d] = v;
                }
            }
        }
}

// Fused launch: z=0 -> zero-fill workers (complementary DRAM-bound work,
// co-resident with tensor-bound gemm CTAs); z=1..3 -> Q/K/V projections.
__global__ __launch_bounds__(256, 3)
void gemm_qkv_zero(const float* __restrict__ xq, const float* __restrict__ xk,
                   const float* __restrict__ xv,
                   const float* __restrict__ wq, const float* __restrict__ wk,
                   const float* __restrict__ wv,
                   const float* __restrict__ bq, const float* __restrict__ bk,
                   const float* __restrict__ bv,
                   float* __restrict__ dq, float* __restrict__ dk,
                   float* __restrict__ dv, float4* __restrict__ p) {
    const int z = blockIdx.z;
    if (z == 0) {
        const int cta = blockIdx.y * gridDim.x + blockIdx.x;
        if (cta < NZCTA) zero_p_body(p, cta, NZCTA);
        return;
    }
    const float* X = (z == 1) ? xq : (z == 2) ? xk : xv;
    const float* W = (z == 1) ? wq : (z == 2) ? wk : wv;
    const float* b = (z == 1) ? bq : (z == 2) ? bk : bv;
    float*       d = (z == 1) ? dq : (z == 2) ? dk : dv;
    gemm_body(X, W, b, d, 1, blockIdx.x, blockIdx.y);
}

__global__ __launch_bounds__(256, 3)
void gemm_out(const float* __restrict__ X, const float* __restrict__ Wt,
              const float* __restrict__ bias, float* __restrict__ out) {
    gemm_body(X, Wt, bias, out, 0, blockIdx.x, blockIdx.y);
}

// ======================================================================
// Banded attention: one CTA = 64 queries x one (b,h). 512 threads.
// (unchanged — measured good)
// ======================================================================
constexpr int SQ_STR  = 68;
constexpr int SKV_STR = 76;
constexpr int SS_STR  = 388;
constexpr int SMEM_ATT = (64 * SQ_STR + 128 * SKV_STR + 64 * SS_STR) * 4;

__global__ __launch_bounds__(512)
void attn_kernel(float* __restrict__ p_out) {
    extern __shared__ char smraw[];
    uint32_t* sQ  = (uint32_t*)smraw;
    uint32_t* sKV = sQ + 64 * SQ_STR;
    float*    sS  = (float*)(sKV + 128 * SKV_STR);

    const int tid  = threadIdx.x;
    const int lane = tid & 31;
    const int warp = tid >> 5;           // 0..15
    const int bh = blockIdx.y;
    const int q0 = blockIdx.x * 64;
    const int klo = max(0, q0 - RAD);
    const int khi = min(SEQ, q0 + 64 + RAD);
    const int Wd  = khi - klo;
    const int nch = (Wd + 127) >> 7;

    const float* Qg = g_q + ((size_t)bh * SEQ + q0) * DK;
    const float* Kg = g_k + (size_t)bh * SEQ * DK;
    const float* Vg = g_v + (size_t)bh * SEQ * DK;

    // load Q (64 x 64), cvt to tf32 bits
    {
        const int r = tid >> 4, c = (tid & 15) << 2;
#pragma unroll
        for (int i = 0; i < 2; i++) {
            const float4 v = *(const float4*)&Qg[(size_t)(r + 32 * i) * DK + c];
            uint4 u;
            u.x = f2tf32(v.x); u.y = f2tf32(v.y); u.z = f2tf32(v.z); u.w = f2tf32(v.w);
            *(uint4*)&sQ[(r + 32 * i) * SQ_STR + c] = u;
        }
    }

    const int wr = warp >> 2;   // 0..3 : row group (16 rows)
    const int wc = warp & 3;    // 0..3 : col group

    // ---- scores: S = (Q @ K^T) * (1/8) into sS ----
    for (int ci = 0; ci < nch; ci++) {
        const int ck0 = klo + (ci << 7);
        const int cw  = min(128, khi - ck0);
        __syncthreads();
        {
            const int r = tid >> 4, c = (tid & 15) << 2;
#pragma unroll
            for (int i = 0; i < 4; i++) {
                const int rr = r + (i << 5);
                float4 v = make_float4(0.f, 0.f, 0.f, 0.f);
                if (rr < cw) v = *(const float4*)&Kg[(size_t)(ck0 + rr) * DK + c];
                uint4 u;
                u.x = f2tf32(v.x); u.y = f2tf32(v.y); u.z = f2tf32(v.z); u.w = f2tf32(v.w);
                *(uint4*)&sKV[rr * SKV_STR + c] = u;
            }
        }
        __syncthreads();

        float sacc[4][4];
#pragma unroll
        for (int j = 0; j < 4; j++)
#pragma unroll
            for (int e = 0; e < 4; e++) sacc[j][e] = 0.f;

#pragma unroll
        for (int kk = 0; kk < 64; kk += 8) {
            uint32_t af[4], bf[4][2];
            {
                const int r = wr * 16 + (lane >> 2);
                const int c = kk + (lane & 3);
                af[0] = sQ[r * SQ_STR + c];
                af[1] = sQ[(r + 8) * SQ_STR + c];
                af[2] = sQ[r * SQ_STR + c + 4];
                af[3] = sQ[(r + 8) * SQ_STR + c + 4];
            }
#pragma unroll
            for (int nt = 0; nt < 4; nt++) {
                const int key = wc * 32 + nt * 8 + (lane >> 2);
                const int kd  = kk + (lane & 3);
                bf[nt][0] = sKV[key * SKV_STR + kd];
                bf[nt][1] = sKV[key * SKV_STR + kd + 4];
            }
#pragma unroll
            for (int nt = 0; nt < 4; nt++) mma8(sacc[nt], af, bf[nt]);
        }
#pragma unroll
        for (int nt = 0; nt < 4; nt++) {
#pragma unroll
            for (int e = 0; e < 4; e++) {
                const int r = wr * 16 + (lane >> 2) + ((e >> 1) << 3);
                const int c = (ci << 7) + wc * 32 + nt * 8 + ((lane & 3) << 1) + (e & 1);
                sS[r * SS_STR + c] = sacc[nt][e] * 0.125f;
            }
        }
    }
    __syncthreads();

    // ---- softmax over the band; zero out-of-band inside window ----
#pragma unroll
    for (int rr = 0; rr < 4; rr++) {
        const int row = warp * 4 + rr;
        const int qi  = q0 + row;
        const int c0  = max(0, qi - RAD) - klo;
        const int c1  = min(SEQ - 1, qi + RAD) - klo;   // inclusive
        float mx = -1e30f;
        for (int c = c0 + lane; c <= c1; c += 32) mx = fmaxf(mx, sS[row * SS_STR + c]);
#pragma unroll
        for (int o = 16; o; o >>= 1) mx = fmaxf(mx, __shfl_xor_sync(0xffffffffu, mx, o));
        float sum = 0.f;
        for (int c = c0 + lane; c <= c1; c += 32) {
            const float e = __expf(sS[row * SS_STR + c] - mx);
            sS[row * SS_STR + c] = e;
            sum += e;
        }
#pragma unroll
        for (int o = 16; o; o >>= 1) sum += __shfl_xor_sync(0xffffffffu, sum, o);
        const float inv = 1.f / sum;
        for (int c = c0 + lane; c <= c1; c += 32) sS[row * SS_STR + c] *= inv;
        for (int c = lane; c < c0; c += 32) sS[row * SS_STR + c] = 0.f;
        for (int c = c1 + 1 + lane; c < Wd; c += 32) sS[row * SS_STR + c] = 0.f;
    }

    // ---- write p_attn window slice ----
    {
        float* Pg = p_out + ((size_t)bh * SEQ + q0) * SEQ + klo;
        const int Wd4 = Wd >> 2;
#pragma unroll
        for (int rr = 0; rr < 4; rr++) {
            const int row = warp * 4 + rr;
            for (int c4 = lane; c4 < Wd4; c4 += 32) {
                __stcs((float4*)&Pg[(size_t)row * SEQ + (c4 << 2)],
                       *(float4*)&sS[row * SS_STR + (c4 << 2)]);
            }
        }
    }

    // ---- O = P @ V (64 x 64), V streamed in chunks into sKV ----
    float oacc[2][4];
#pragma unroll
    for (int j = 0; j < 2; j++)
#pragma unroll
        for (int e = 0; e < 4; e++) oacc[j][e] = 0.f;

    for (int ci = 0; ci < nch; ci++) {
        const int ck0 = klo + (ci << 7);
        const int cw  = min(128, khi - ck0);
        __syncthreads();
        {
            const int r = tid >> 4, c = (tid & 15) << 2;
#pragma unroll
            for (int i = 0; i < 4; i++) {
                const int rr = r + (i << 5);
                float4 v = make_float4(0.f, 0.f, 0.f, 0.f);
                if (rr < cw) v = *(const float4*)&Vg[(size_t)(ck0 + rr) * DK + c];
                uint4 u;
                u.x = f2tf32(v.x); u.y = f2tf32(v.y); u.z = f2tf32(v.z); u.w = f2tf32(v.w);
                *(uint4*)&sKV[rr * SKV_STR + c] = u;
            }
        }
        __syncthreads();

#pragma unroll
        for (int kk = 0; kk < 128; kk += 8) {
            uint32_t af[4], bf[2][2];
            {
                const int r = wr * 16 + (lane >> 2);
                const int c = (ci << 7) + kk + (lane & 3);
                af[0] = f2tf32(sS[r * SS_STR + c]);
                af[1] = f2tf32(sS[(r + 8) * SS_STR + c]);
                af[2] = f2tf32(sS[r * SS_STR + c + 4]);
                af[3] = f2tf32(sS[(r + 8) * SS_STR + c + 4]);
            }
#pragma unroll
            for (int nt = 0; nt < 2; nt++) {
                const int n  = wc * 16 + nt * 8 + (lane >> 2);
                const int kd = kk + (lane & 3);
                bf[nt][0] = sKV[kd * SKV_STR + n];
                bf[nt][1] = sKV[(kd + 4) * SKV_STR + n];
            }
#pragma unroll
            for (int nt = 0; nt < 2; nt++) mma8(oacc[nt], af, bf[nt]);
        }
    }

    // ---- write X in [B,S,D] (head-concat) layout ----
    {
        const int b = bh >> 4, h = bh & 15;
#pragma unroll
        for (int nt = 0; nt < 2; nt++) {
#pragma unroll
            for (int e = 0; e < 4; e++) {
                const int r = wr * 16 + (lane >> 2) + ((e >> 1) << 3);
                const int c = wc * 16 + nt * 8 + ((lane & 3) << 1) + (e & 1);
                g_x[((size_t)b * SEQ + q0 + r) * DM + (h << 6) + c] = oacc[nt][e];
            }
        }
    }
}

// ======================================================================
// Launch
// ======================================================================
extern "C" void kernel_launch(void* const* d_in, const int* in_sizes, int n_in,
                              void* d_out, int out_size) {
    const float* query = (const float*)d_in[0];
    const float* key_  = (const float*)d_in[1];
    const float* value = (const float*)d_in[2];
    const float* Wq = (const float*)d_in[3];
    const float* bq = (const float*)d_in[4];
    const float* Wk = (const float*)d_in[5];
    const float* bk = (const float*)d_in[6];
    const float* Wv = (const float*)d_in[7];
    const float* bv = (const float*)d_in[8];
    const float* Wo = (const float*)d_in[9];
    const float* bo = (const float*)d_in[10];

    float* out = (float*)d_out;
    float* p   = out + (size_t)NBATCH * SEQ * DM;

    float *qp, *kp, *vp, *xp;
    cudaGetSymbolAddress((void**)&qp, g_q);
    cudaGetSymbolAddress((void**)&kp, g_k);
    cudaGetSymbolAddress((void**)&vp, g_v);
    cudaGetSymbolAddress((void**)&xp, g_x);

    cudaFuncSetAttribute((const void*)attn_kernel,
                         cudaFuncAttributeMaxDynamicSharedMemorySize, SMEM_ATT);

    // z=0: zero-fill of p outside the attention windows (overlapped with
    // the tensor-bound projection GEMMs); z=1..3: Q/K/V projections.
    gemm_qkv_zero<<<dim3(DM / 64, NROW / 128, 4), 256>>>(
        query, key_, value, Wq, Wk, Wv, bq, bk, bv, qp, kp, vp, (float4*)p);

    attn_kernel<<<dim3(SEQ / 64, NBATCH * NH), 512, SMEM_ATT>>>(p);

    gemm_out<<<dim3(DM / 64, NROW / 128), 256>>>(xp, Wo, bo, out);
}

// round 10
// speedup vs baseline: 1.0898x; 1.0898x over previous
#include <cuda_runtime.h>
#include <cstdint>
#include <math.h>

#define DI __device__ __forceinline__

constexpr int SEQ = 2048;
constexpr int DM  = 1024;
constexpr int NH  = 16;
constexpr int DK  = 64;
constexpr int RAD = 128;          // masksize // 2
constexpr int NBATCH = 2;
constexpr int NROW = NBATCH * SEQ;   // 4096 rows for all projections
constexpr int NZCTA = 256;           // zero-fill worker CTAs (z=0 plane)

// ---------------- scratch (no allocation allowed) ----------------
__device__ __align__(256) float g_q[NBATCH * NH * SEQ * DK];
__device__ __align__(256) float g_k[NBATCH * NH * SEQ * DK];
__device__ __align__(256) float g_v[NBATCH * NH * SEQ * DK];
__device__ __align__(256) float g_x[NBATCH * SEQ * DM];

// ---------------- tf32 helpers ----------------
DI uint32_t f2tf32(float x) {
    uint32_t r;
    asm("cvt.rna.tf32.f32 %0, %1;" : "=r"(r) : "f"(x));
    return r;
}

DI void mma8(float* d, const uint32_t* a, const uint32_t* b) {
    asm volatile(
        "mma.sync.aligned.m16n8k8.row.col.f32.tf32.tf32.f32 "
        "{%0,%1,%2,%3}, {%4,%5,%6,%7}, {%8,%9}, {%0,%1,%2,%3};\n"
        : "+f"(d[0]), "+f"(d[1]), "+f"(d[2]), "+f"(d[3])
        : "r"(a[0]), "r"(a[1]), "r"(a[2]), "r"(a[3]),
          "r"(b[0]), "r"(b[1]));
}

// ---------------- zero-fill body (p outside the attention windows) -----
DI void zero_p_body(float4* __restrict__ p, int cta, int ncta) {
    const size_t total = (size_t)32 * SEQ * (SEQ / 4);   // 33.5M float4
    const float4 z = make_float4(0.f, 0.f, 0.f, 0.f);
    const size_t stride = (size_t)ncta * 256;
    for (size_t i = (size_t)cta * 256 + threadIdx.x; i < total; i += stride) {
        const int col = ((int)(i & 511)) << 2;          // 0..2044 step 4
        const int row = (int)((i >> 9) & (SEQ - 1));
        const int q0  = row & ~63;
        const int klo = max(0, q0 - RAD);
        const int khi = min(SEQ, q0 + 64 + RAD);
        if (col >= klo && col < khi) continue;          // attn writes the window
        __stcs(&p[i], z);
    }
}

// ======================================================================
// GEMM body (R7-proven config): out = X[4096,1024] @ W[1024,1024] + bias
// BM=128, BN=128, BK=32, 256 threads (8 warps as 2x4), warp tile 64x32.
// __launch_bounds__(256,2) on callers -> 128 regs, 2 CTAs/SM.
// mode 0: out[r*1024 + c]; mode 1: head-scatter to [B,H,S,dk]
// ======================================================================
DI void gemm_body(const float* __restrict__ X, const float* __restrict__ Wt,
                  const float* __restrict__ bias, float* __restrict__ out,
                  int mode, int bx, int by) {
    __shared__ uint32_t As[128 * 36];   // stride 36 (mod 32 == 4 -> conflict-free)
    __shared__ uint32_t Bs[32 * 136];   // stride 136 (mod 32 == 8 -> conflict-free)

    const int tid  = threadIdx.x;
    const int lane = tid & 31;
    const int warp = tid >> 5;
    const int row0 = by * 128;
    const int col0 = bx * 128;
    const int wm = (warp >> 2) * 64;   // 0 or 64
    const int wn = (warp & 3) * 32;    // 0..96

    float acc[4][4][4];
#pragma unroll
    for (int i = 0; i < 4; i++)
#pragma unroll
        for (int j = 0; j < 4; j++)
#pragma unroll
            for (int e = 0; e < 4; e++) acc[i][j][e] = 0.f;

    const int ar = tid >> 3,  ac = (tid & 7) << 2;    // A: 32 rows/pass x 32 cols
    const int br = tid >> 5,  bc = (tid & 31) << 2;   // B: 8 rows/pass x 128 cols

    for (int kt = 0; kt < DM; kt += 32) {
#pragma unroll
        for (int i = 0; i < 4; i++) {
            const float4 v = *(const float4*)&X[(size_t)(row0 + ar + 32 * i) * DM + kt + ac];
            uint4 u;
            u.x = f2tf32(v.x); u.y = f2tf32(v.y); u.z = f2tf32(v.z); u.w = f2tf32(v.w);
            *(uint4*)&As[(ar + 32 * i) * 36 + ac] = u;
        }
#pragma unroll
        for (int i = 0; i < 4; i++) {
            const float4 v = *(const float4*)&Wt[(size_t)(kt + br + 8 * i) * DM + col0 + bc];
            uint4 u;
            u.x = f2tf32(v.x); u.y = f2tf32(v.y); u.z = f2tf32(v.z); u.w = f2tf32(v.w);
            *(uint4*)&Bs[(br + 8 * i) * 136 + bc] = u;
        }
        __syncthreads();

#pragma unroll
        for (int kk = 0; kk < 32; kk += 8) {
            uint32_t af[4][4], bf[4][2];
#pragma unroll
            for (int mt = 0; mt < 4; mt++) {
                const int r = wm + mt * 16 + (lane >> 2);
                const int c = kk + (lane & 3);
                af[mt][0] = As[r * 36 + c];
                af[mt][1] = As[(r + 8) * 36 + c];
                af[mt][2] = As[r * 36 + c + 4];
                af[mt][3] = As[(r + 8) * 36 + c + 4];
            }
#pragma unroll
            for (int nt = 0; nt < 4; nt++) {
                const int cB = wn + nt * 8 + (lane >> 2);
                const int rB = kk + (lane & 3);
                bf[nt][0] = Bs[rB * 136 + cB];
                bf[nt][1] = Bs[(rB + 4) * 136 + cB];
            }
#pragma unroll
            for (int mt = 0; mt < 4; mt++)
#pragma unroll
                for (int nt = 0; nt < 4; nt++) mma8(acc[mt][nt], af[mt], bf[nt]);
        }
        __syncthreads();
    }

    // epilogue
#pragma unroll
    for (int mt = 0; mt < 4; mt++)
#pragma unroll
        for (int nt = 0; nt < 4; nt++) {
            const int r0 = row0 + wm + mt * 16 + (lane >> 2);
            const int c0 = col0 + wn + nt * 8 + ((lane & 3) << 1);
#pragma unroll
            for (int e = 0; e < 4; e++) {
                const int r = r0 + ((e >> 1) << 3);
                const int c = c0 + (e & 1);
                const float v = acc[mt][nt][e] + bias[c];
                if (mode == 0) {
                    out[(size_t)r * DM + c] = v;
                } else {
                    const int b = r >> 11, s2 = r & (SEQ - 1);
                    const int h = c >> 6,  d = c & 63;
                    out[((((size_t)b * NH + h) * SEQ + s2) << 6) + d] = v;
                }
            }
        }
}

// Fused launch: z=0 -> zero-fill workers (DRAM-bound, co-resident with the
// tensor-bound gemm CTAs); z=1..3 -> Q/K/V projections (R7 tile config).
__global__ __launch_bounds__(256, 2)
void gemm_qkv_zero(const float* __restrict__ xq, const float* __restrict__ xk,
                   const float* __restrict__ xv,
                   const float* __restrict__ wq, const float* __restrict__ wk,
                   const float* __restrict__ wv,
                   const float* __restrict__ bq, const float* __restrict__ bk,
                   const float* __restrict__ bv,
                   float* __restrict__ dq, float* __restrict__ dk,
                   float* __restrict__ dv, float4* __restrict__ p) {
    const int z = blockIdx.z;
    if (z == 0) {
        const int cta = blockIdx.y * gridDim.x + blockIdx.x;   // 0..255
        if (cta < NZCTA) zero_p_body(p, cta, NZCTA);
        return;
    }
    const float* X = (z == 1) ? xq : (z == 2) ? xk : xv;
    const float* W = (z == 1) ? wq : (z == 2) ? wk : wv;
    const float* b = (z == 1) ? bq : (z == 2) ? bk : bv;
    float*       d = (z == 1) ? dq : (z == 2) ? dk : dv;
    gemm_body(X, W, b, d, 1, blockIdx.x, blockIdx.y);
}

__global__ __launch_bounds__(256, 2)
void gemm_out(const float* __restrict__ X, const float* __restrict__ Wt,
              const float* __restrict__ bias, float* __restrict__ out) {
    gemm_body(X, Wt, bias, out, 0, blockIdx.x, blockIdx.y);
}

// ======================================================================
// Banded attention: one CTA = 64 queries x one (b,h). 512 threads.
// (unchanged — measured good)
// ======================================================================
constexpr int SQ_STR  = 68;
constexpr int SKV_STR = 76;
constexpr int SS_STR  = 388;
constexpr int SMEM_ATT = (64 * SQ_STR + 128 * SKV_STR + 64 * SS_STR) * 4;

__global__ __launch_bounds__(512)
void attn_kernel(float* __restrict__ p_out) {
    extern __shared__ char smraw[];
    uint32_t* sQ  = (uint32_t*)smraw;
    uint32_t* sKV = sQ + 64 * SQ_STR;
    float*    sS  = (float*)(sKV + 128 * SKV_STR);

    const int tid  = threadIdx.x;
    const int lane = tid & 31;
    const int warp = tid >> 5;           // 0..15
    const int bh = blockIdx.y;
    const int q0 = blockIdx.x * 64;
    const int klo = max(0, q0 - RAD);
    const int khi = min(SEQ, q0 + 64 + RAD);
    const int Wd  = khi - klo;
    const int nch = (Wd + 127) >> 7;

    const float* Qg = g_q + ((size_t)bh * SEQ + q0) * DK;
    const float* Kg = g_k + (size_t)bh * SEQ * DK;
    const float* Vg = g_v + (size_t)bh * SEQ * DK;

    // load Q (64 x 64), cvt to tf32 bits
    {
        const int r = tid >> 4, c = (tid & 15) << 2;
#pragma unroll
        for (int i = 0; i < 2; i++) {
            const float4 v = *(const float4*)&Qg[(size_t)(r + 32 * i) * DK + c];
            uint4 u;
            u.x = f2tf32(v.x); u.y = f2tf32(v.y); u.z = f2tf32(v.z); u.w = f2tf32(v.w);
            *(uint4*)&sQ[(r + 32 * i) * SQ_STR + c] = u;
        }
    }

    const int wr = warp >> 2;   // 0..3 : row group (16 rows)
    const int wc = warp & 3;    // 0..3 : col group

    // ---- scores: S = (Q @ K^T) * (1/8) into sS ----
    for (int ci = 0; ci < nch; ci++) {
        const int ck0 = klo + (ci << 7);
        const int cw  = min(128, khi - ck0);
        __syncthreads();
        {
            const int r = tid >> 4, c = (tid & 15) << 2;
#pragma unroll
            for (int i = 0; i < 4; i++) {
                const int rr = r + (i << 5);
                float4 v = make_float4(0.f, 0.f, 0.f, 0.f);
                if (rr < cw) v = *(const float4*)&Kg[(size_t)(ck0 + rr) * DK + c];
                uint4 u;
                u.x = f2tf32(v.x); u.y = f2tf32(v.y); u.z = f2tf32(v.z); u.w = f2tf32(v.w);
                *(uint4*)&sKV[rr * SKV_STR + c] = u;
            }
        }
        __syncthreads();

        float sacc[4][4];
#pragma unroll
        for (int j = 0; j < 4; j++)
#pragma unroll
            for (int e = 0; e < 4; e++) sacc[j][e] = 0.f;

#pragma unroll
        for (int kk = 0; kk < 64; kk += 8) {
            uint32_t af[4], bf[4][2];
            {
                const int r = wr * 16 + (lane >> 2);
                const int c = kk + (lane & 3);
                af[0] = sQ[r * SQ_STR + c];
                af[1] = sQ[(r + 8) * SQ_STR + c];
                af[2] = sQ[r * SQ_STR + c + 4];
                af[3] = sQ[(r + 8) * SQ_STR + c + 4];
            }
#pragma unroll
            for (int nt = 0; nt < 4; nt++) {
                const int key = wc * 32 + nt * 8 + (lane >> 2);
                const int kd  = kk + (lane & 3);
                bf[nt][0] = sKV[key * SKV_STR + kd];
                bf[nt][1] = sKV[key * SKV_STR + kd + 4];
            }
#pragma unroll
            for (int nt = 0; nt < 4; nt++) mma8(sacc[nt], af, bf[nt]);
        }
#pragma unroll
        for (int nt = 0; nt < 4; nt++) {
#pragma unroll
            for (int e = 0; e < 4; e++) {
                const int r = wr * 16 + (lane >> 2) + ((e >> 1) << 3);
                const int c = (ci << 7) + wc * 32 + nt * 8 + ((lane & 3) << 1) + (e & 1);
                sS[r * SS_STR + c] = sacc[nt][e] * 0.125f;
            }
        }
    }
    __syncthreads();

    // ---- softmax over the band; zero out-of-band inside window ----
#pragma unroll
    for (int rr = 0; rr < 4; rr++) {
        const int row = warp * 4 + rr;
        const int qi  = q0 + row;
        const int c0  = max(0, qi - RAD) - klo;
        const int c1  = min(SEQ - 1, qi + RAD) - klo;   // inclusive
        float mx = -1e30f;
        for (int c = c0 + lane; c <= c1; c += 32) mx = fmaxf(mx, sS[row * SS_STR + c]);
#pragma unroll
        for (int o = 16; o; o >>= 1) mx = fmaxf(mx, __shfl_xor_sync(0xffffffffu, mx, o));
        float sum = 0.f;
        for (int c = c0 + lane; c <= c1; c += 32) {
            const float e = __expf(sS[row * SS_STR + c] - mx);
            sS[row * SS_STR + c] = e;
            sum += e;
        }
#pragma unroll
        for (int o = 16; o; o >>= 1) sum += __shfl_xor_sync(0xffffffffu, sum, o);
        const float inv = 1.f / sum;
        for (int c = c0 + lane; c <= c1; c += 32) sS[row * SS_STR + c] *= inv;
        for (int c = lane; c < c0; c += 32) sS[row * SS_STR + c] = 0.f;
        for (int c = c1 + 1 + lane; c < Wd; c += 32) sS[row * SS_STR + c] = 0.f;
    }

    // ---- write p_attn window slice ----
    {
        float* Pg = p_out + ((size_t)bh * SEQ + q0) * SEQ + klo;
        const int Wd4 = Wd >> 2;
#pragma unroll
        for (int rr = 0; rr < 4; rr++) {
            const int row = warp * 4 + rr;
            for (int c4 = lane; c4 < Wd4; c4 += 32) {
                __stcs((float4*)&Pg[(size_t)row * SEQ + (c4 << 2)],
                       *(float4*)&sS[row * SS_STR + (c4 << 2)]);
            }
        }
    }

    // ---- O = P @ V (64 x 64), V streamed in chunks into sKV ----
    float oacc[2][4];
#pragma unroll
    for (int j = 0; j < 2; j++)
#pragma unroll
        for (int e = 0; e < 4; e++) oacc[j][e] = 0.f;

    for (int ci = 0; ci < nch; ci++) {
        const int ck0 = klo + (ci << 7);
        const int cw  = min(128, khi - ck0);
        __syncthreads();
        {
            const int r = tid >> 4, c = (tid & 15) << 2;
#pragma unroll
            for (int i = 0; i < 4; i++) {
                const int rr = r + (i << 5);
                float4 v = make_float4(0.f, 0.f, 0.f, 0.f);
                if (rr < cw) v = *(const float4*)&Vg[(size_t)(ck0 + rr) * DK + c];
                uint4 u;
                u.x = f2tf32(v.x); u.y = f2tf32(v.y); u.z = f2tf32(v.z); u.w = f2tf32(v.w);
                *(uint4*)&sKV[rr * SKV_STR + c] = u;
            }
        }
        __syncthreads();

#pragma unroll
        for (int kk = 0; kk < 128; kk += 8) {
            uint32_t af[4], bf[2][2];
            {
                const int r = wr * 16 + (lane >> 2);
                const int c = (ci << 7) + kk + (lane & 3);
                af[0] = f2tf32(sS[r * SS_STR + c]);
                af[1] = f2tf32(sS[(r + 8) * SS_STR + c]);
                af[2] = f2tf32(sS[r * SS_STR + c + 4]);
                af[3] = f2tf32(sS[(r + 8) * SS_STR + c + 4]);
            }
#pragma unroll
            for (int nt = 0; nt < 2; nt++) {
                const int n  = wc * 16 + nt * 8 + (lane >> 2);
                const int kd = kk + (lane & 3);
                bf[nt][0] = sKV[kd * SKV_STR + n];
                bf[nt][1] = sKV[(kd + 4) * SKV_STR + n];
            }
#pragma unroll
            for (int nt = 0; nt < 2; nt++) mma8(oacc[nt], af, bf[nt]);
        }
    }

    // ---- write X in [B,S,D] (head-concat) layout ----
    {
        const int b = bh >> 4, h = bh & 15;
#pragma unroll
        for (int nt = 0; nt < 2; nt++) {
#pragma unroll
            for (int e = 0; e < 4; e++) {
                const int r = wr * 16 + (lane >> 2) + ((e >> 1) << 3);
                const int c = wc * 16 + nt * 8 + ((lane & 3) << 1) + (e & 1);
                g_x[((size_t)b * SEQ + q0 + r) * DM + (h << 6) + c] = oacc[nt][e];
            }
        }
    }
}

// ======================================================================
// Launch
// ======================================================================
extern "C" void kernel_launch(void* const* d_in, const int* in_sizes, int n_in,
                              void* d_out, int out_size) {
    const float* query = (const float*)d_in[0];
    const float* key_  = (const float*)d_in[1];
    const float* value = (const float*)d_in[2];
    const float* Wq = (const float*)d_in[3];
    const float* bq = (const float*)d_in[4];
    const float* Wk = (const float*)d_in[5];
    const float* bk = (const float*)d_in[6];
    const float* Wv = (const float*)d_in[7];
    const float* bv = (const float*)d_in[8];
    const float* Wo = (const float*)d_in[9];
    const float* bo = (const float*)d_in[10];

    float* out = (float*)d_out;
    float* p   = out + (size_t)NBATCH * SEQ * DM;

    float *qp, *kp, *vp, *xp;
    cudaGetSymbolAddress((void**)&qp, g_q);
    cudaGetSymbolAddress((void**)&kp, g_k);
    cudaGetSymbolAddress((void**)&vp, g_v);
    cudaGetSymbolAddress((void**)&xp, g_x);

    cudaFuncSetAttribute((const void*)attn_kernel,
                         cudaFuncAttributeMaxDynamicSharedMemorySize, SMEM_ATT);

    // z=0: zero-fill of p outside attention windows (overlapped with the
    // tensor-bound projection GEMMs); z=1..3: Q/K/V projections.
    gemm_qkv_zero<<<dim3(DM / 128, NROW / 128, 4), 256>>>(
        query, key_, value, Wq, Wk, Wv, bq, bk, bv, qp, kp, vp, (float4*)p);

    attn_kernel<<<dim3(SEQ / 64, NBATCH * NH), 512, SMEM_ATT>>>(p);

    gemm_out<<<dim3(DM / 128, NROW / 128), 256>>>(xp, Wo, bo, out);
}

// round 11
// speedup vs baseline: 1.1086x; 1.0173x over previous
#include <cuda_runtime.h>
#include <cstdint>
#include <math.h>

#define DI __device__ __forceinline__

constexpr int SEQ = 2048;
constexpr int DM  = 1024;
constexpr int NH  = 16;
constexpr int DK  = 64;
constexpr int RAD = 128;          // masksize // 2
constexpr int NBATCH = 2;
constexpr int NROW = NBATCH * SEQ;   // 4096 rows for all projections
constexpr int NZCTA = 256;           // zero-fill worker CTAs (z=0 plane)

// ---------------- scratch (no allocation allowed) ----------------
__device__ __align__(256) float g_q[NBATCH * NH * SEQ * DK];
__device__ __align__(256) float g_k[NBATCH * NH * SEQ * DK];
__device__ __align__(256) float g_v[NBATCH * NH * SEQ * DK];
__device__ __align__(256) float g_x[NBATCH * SEQ * DM];

// ---------------- tf32 / cp.async helpers ----------------
DI uint32_t f2tf32(float x) {
    uint32_t r;
    asm("cvt.rna.tf32.f32 %0, %1;" : "=r"(r) : "f"(x));
    return r;
}

DI void mma8(float* d, const uint32_t* a, const uint32_t* b) {
    asm volatile(
        "mma.sync.aligned.m16n8k8.row.col.f32.tf32.tf32.f32 "
        "{%0,%1,%2,%3}, {%4,%5,%6,%7}, {%8,%9}, {%0,%1,%2,%3};\n"
        : "+f"(d[0]), "+f"(d[1]), "+f"(d[2]), "+f"(d[3])
        : "r"(a[0]), "r"(a[1]), "r"(a[2]), "r"(a[3]),
          "r"(b[0]), "r"(b[1]));
}

DI uint32_t smem_u32(const void* p) {
    return (uint32_t)__cvta_generic_to_shared(p);
}
DI void cp16(uint32_t dst, const void* src) {
    asm volatile("cp.async.cg.shared.global [%0], [%1], 16;\n" :: "r"(dst), "l"(src));
}
DI void cp_commit() { asm volatile("cp.async.commit_group;\n" ::: "memory"); }
DI void cp_wait0()  { asm volatile("cp.async.wait_group 0;\n" ::: "memory"); }

// ---------------- zero-fill body (p outside the attention windows) -----
DI void zero_p_body(float4* __restrict__ p, int cta, int ncta) {
    const size_t total = (size_t)32 * SEQ * (SEQ / 4);   // 33.5M float4
    const float4 z = make_float4(0.f, 0.f, 0.f, 0.f);
    const size_t stride = (size_t)ncta * 256;
    for (size_t i = (size_t)cta * 256 + threadIdx.x; i < total; i += stride) {
        const int col = ((int)(i & 511)) << 2;          // 0..2044 step 4
        const int row = (int)((i >> 9) & (SEQ - 1));
        const int q0  = row & ~63;
        const int klo = max(0, q0 - RAD);
        const int khi = min(SEQ, q0 + 64 + RAD);
        if (col >= klo && col < khi) continue;          // attn writes the window
        __stcs(&p[i], z);
    }
}

// ======================================================================
// GEMM body: out = X[4096,1024] @ W[1024,1024] + bias
// cp.async double-buffered smem (raw fp32, cvt after LDS), 1 barrier/iter.
// BM=128, BN=128, BK=32, 256 threads (8 warps as 2x4), warp tile 64x32.
// 2 stages x 35.8KB = 71.7KB dynamic smem -> still 2 CTAs/SM; regs ~115.
// mode 0: out[r*1024 + c]; mode 1: head-scatter to [B,H,S,dk]
// ======================================================================
constexpr int GA_STR  = 36;                 // mod 32 == 4 -> conflict-free A frags
constexpr int GB_STR  = 136;                // mod 32 == 8 -> conflict-free B frags
constexpr int GA_F    = 128 * GA_STR;       // 4608 floats
constexpr int GB_F    = 32 * GB_STR;        // 4352 floats
constexpr int STAGE_F = GA_F + GB_F;        // 8960 floats
constexpr int SMEM_GEMM = 2 * STAGE_F * 4;  // 71680 B

DI void gemm_body(const float* __restrict__ X, const float* __restrict__ Wt,
                  const float* __restrict__ bias, float* __restrict__ out,
                  int mode, int bx, int by) {
    extern __shared__ float gsm[];

    const int tid  = threadIdx.x;
    const int lane = tid & 31;
    const int warp = tid >> 5;
    const int row0 = by * 128;
    const int col0 = bx * 128;
    const int wm = (warp >> 2) * 64;   // 0 or 64
    const int wn = (warp & 3) * 32;    // 0..96

    float acc[4][4][4];
#pragma unroll
    for (int i = 0; i < 4; i++)
#pragma unroll
        for (int j = 0; j < 4; j++)
#pragma unroll
            for (int e = 0; e < 4; e++) acc[i][j][e] = 0.f;

    const int ar = tid >> 3,  ac = (tid & 7) << 2;    // A: 32 rows/pass x 32 cols
    const int br = tid >> 5,  bc = (tid & 31) << 2;   // B: 8 rows/pass x 128 cols

    // prologue: tile 0 -> stage 0
    {
        float* stg = gsm;
#pragma unroll
        for (int i = 0; i < 4; i++)
            cp16(smem_u32(&stg[(ar + 32 * i) * GA_STR + ac]),
                 &X[(size_t)(row0 + ar + 32 * i) * DM + ac]);
#pragma unroll
        for (int i = 0; i < 4; i++)
            cp16(smem_u32(&stg[GA_F + (br + 8 * i) * GB_STR + bc]),
                 &Wt[(size_t)(br + 8 * i) * DM + col0 + bc]);
        cp_commit();
    }

    for (int kt = 0; kt < 32; kt++) {
        cp_wait0();            // tile kt landed (issued one full iter ago)
        __syncthreads();       // visibility + guards stage[kt+1 & 1] overwrite

        if (kt < 31) {         // issue next tile; overlaps the mma block below
            const int k0 = (kt + 1) << 5;
            float* stg = gsm + ((kt + 1) & 1) * STAGE_F;
#pragma unroll
            for (int i = 0; i < 4; i++)
                cp16(smem_u32(&stg[(ar + 32 * i) * GA_STR + ac]),
                     &X[(size_t)(row0 + ar + 32 * i) * DM + k0 + ac]);
#pragma unroll
            for (int i = 0; i < 4; i++)
                cp16(smem_u32(&stg[GA_F + (br + 8 * i) * GB_STR + bc]),
                     &Wt[(size_t)(k0 + br + 8 * i) * DM + col0 + bc]);
            cp_commit();
        }

        const float* As = gsm + (kt & 1) * STAGE_F;
        const float* Bs = As + GA_F;
#pragma unroll
        for (int kk = 0; kk < 32; kk += 8) {
            uint32_t af[4][4], bf[4][2];
#pragma unroll
            for (int mt = 0; mt < 4; mt++) {
                const int r = wm + mt * 16 + (lane >> 2);
                const int c = kk + (lane & 3);
                af[mt][0] = f2tf32(As[r * GA_STR + c]);
                af[mt][1] = f2tf32(As[(r + 8) * GA_STR + c]);
                af[mt][2] = f2tf32(As[r * GA_STR + c + 4]);
                af[mt][3] = f2tf32(As[(r + 8) * GA_STR + c + 4]);
            }
#pragma unroll
            for (int nt = 0; nt < 4; nt++) {
                const int cB = wn + nt * 8 + (lane >> 2);
                const int rB = kk + (lane & 3);
                bf[nt][0] = f2tf32(Bs[rB * GB_STR + cB]);
                bf[nt][1] = f2tf32(Bs[(rB + 4) * GB_STR + cB]);
            }
#pragma unroll
            for (int mt = 0; mt < 4; mt++)
#pragma unroll
                for (int nt = 0; nt < 4; nt++) mma8(acc[mt][nt], af[mt], bf[nt]);
        }
    }

    // epilogue
#pragma unroll
    for (int mt = 0; mt < 4; mt++)
#pragma unroll
        for (int nt = 0; nt < 4; nt++) {
            const int r0 = row0 + wm + mt * 16 + (lane >> 2);
            const int c0 = col0 + wn + nt * 8 + ((lane & 3) << 1);
#pragma unroll
            for (int e = 0; e < 4; e++) {
                const int r = r0 + ((e >> 1) << 3);
                const int c = c0 + (e & 1);
                const float v = acc[mt][nt][e] + bias[c];
                if (mode == 0) {
                    out[(size_t)r * DM + c] = v;
                } else {
                    const int b = r >> 11, s2 = r & (SEQ - 1);
                    const int h = c >> 6,  d = c & 63;
                    out[((((size_t)b * NH + h) * SEQ + s2) << 6) + d] = v;
                }
            }
        }
}

// Fused launch: z=0 -> zero-fill workers (DRAM-bound, co-resident with the
// tensor-bound gemm CTAs); z=1..3 -> Q/K/V projections.
__global__ __launch_bounds__(256, 2)
void gemm_qkv_zero(const float* __restrict__ xq, const float* __restrict__ xk,
                   const float* __restrict__ xv,
                   const float* __restrict__ wq, const float* __restrict__ wk,
                   const float* __restrict__ wv,
                   const float* __restrict__ bq, const float* __restrict__ bk,
                   const float* __restrict__ bv,
                   float* __restrict__ dq, float* __restrict__ dk,
                   float* __restrict__ dv, float4* __restrict__ p) {
    const int z = blockIdx.z;
    if (z == 0) {
        const int cta = blockIdx.y * gridDim.x + blockIdx.x;   // 0..255
        if (cta < NZCTA) zero_p_body(p, cta, NZCTA);
        return;
    }
    const float* X = (z == 1) ? xq : (z == 2) ? xk : xv;
    const float* W = (z == 1) ? wq : (z == 2) ? wk : wv;
    const float* b = (z == 1) ? bq : (z == 2) ? bk : bv;
    float*       d = (z == 1) ? dq : (z == 2) ? dk : dv;
    gemm_body(X, W, b, d, 1, blockIdx.x, blockIdx.y);
}

__global__ __launch_bounds__(256, 2)
void gemm_out(const float* __restrict__ X, const float* __restrict__ Wt,
              const float* __restrict__ bias, float* __restrict__ out) {
    gemm_body(X, Wt, bias, out, 0, blockIdx.x, blockIdx.y);
}

// ======================================================================
// Banded attention: one CTA = 64 queries x one (b,h). 512 threads.
// (unchanged — measured good)
// ======================================================================
constexpr int SQ_STR  = 68;
constexpr int SKV_STR = 76;
constexpr int SS_STR  = 388;
constexpr int SMEM_ATT = (64 * SQ_STR + 128 * SKV_STR + 64 * SS_STR) * 4;

__global__ __launch_bounds__(512)
void attn_kernel(float* __restrict__ p_out) {
    extern __shared__ char smraw[];
    uint32_t* sQ  = (uint32_t*)smraw;
    uint32_t* sKV = sQ + 64 * SQ_STR;
    float*    sS  = (float*)(sKV + 128 * SKV_STR);

    const int tid  = threadIdx.x;
    const int lane = tid & 31;
    const int warp = tid >> 5;           // 0..15
    const int bh = blockIdx.y;
    const int q0 = blockIdx.x * 64;
    const int klo = max(0, q0 - RAD);
    const int khi = min(SEQ, q0 + 64 + RAD);
    const int Wd  = khi - klo;
    const int nch = (Wd + 127) >> 7;

    const float* Qg = g_q + ((size_t)bh * SEQ + q0) * DK;
    const float* Kg = g_k + (size_t)bh * SEQ * DK;
    const float* Vg = g_v + (size_t)bh * SEQ * DK;

    // load Q (64 x 64), cvt to tf32 bits
    {
        const int r = tid >> 4, c = (tid & 15) << 2;
#pragma unroll
        for (int i = 0; i < 2; i++) {
            const float4 v = *(const float4*)&Qg[(size_t)(r + 32 * i) * DK + c];
            uint4 u;
            u.x = f2tf32(v.x); u.y = f2tf32(v.y); u.z = f2tf32(v.z); u.w = f2tf32(v.w);
            *(uint4*)&sQ[(r + 32 * i) * SQ_STR + c] = u;
        }
    }

    const int wr = warp >> 2;   // 0..3 : row group (16 rows)
    const int wc = warp & 3;    // 0..3 : col group

    // ---- scores: S = (Q @ K^T) * (1/8) into sS ----
    for (int ci = 0; ci < nch; ci++) {
        const int ck0 = klo + (ci << 7);
        const int cw  = min(128, khi - ck0);
        __syncthreads();
        {
            const int r = tid >> 4, c = (tid & 15) << 2;
#pragma unroll
            for (int i = 0; i < 4; i++) {
                const int rr = r + (i << 5);
                float4 v = make_float4(0.f, 0.f, 0.f, 0.f);
                if (rr < cw) v = *(const float4*)&Kg[(size_t)(ck0 + rr) * DK + c];
                uint4 u;
                u.x = f2tf32(v.x); u.y = f2tf32(v.y); u.z = f2tf32(v.z); u.w = f2tf32(v.w);
                *(uint4*)&sKV[rr * SKV_STR + c] = u;
            }
        }
        __syncthreads();

        float sacc[4][4];
#pragma unroll
        for (int j = 0; j < 4; j++)
#pragma unroll
            for (int e = 0; e < 4; e++) sacc[j][e] = 0.f;

#pragma unroll
        for (int kk = 0; kk < 64; kk += 8) {
            uint32_t af[4], bf[4][2];
            {
                const int r = wr * 16 + (lane >> 2);
                const int c = kk + (lane & 3);
                af[0] = sQ[r * SQ_STR + c];
                af[1] = sQ[(r + 8) * SQ_STR + c];
                af[2] = sQ[r * SQ_STR + c + 4];
                af[3] = sQ[(r + 8) * SQ_STR + c + 4];
            }
#pragma unroll
            for (int nt = 0; nt < 4; nt++) {
                const int key = wc * 32 + nt * 8 + (lane >> 2);
                const int kd  = kk + (lane & 3);
                bf[nt][0] = sKV[key * SKV_STR + kd];
                bf[nt][1] = sKV[key * SKV_STR + kd + 4];
            }
#pragma unroll
            for (int nt = 0; nt < 4; nt++) mma8(sacc[nt], af, bf[nt]);
        }
#pragma unroll
        for (int nt = 0; nt < 4; nt++) {
#pragma unroll
            for (int e = 0; e < 4; e++) {
                const int r = wr * 16 + (lane >> 2) + ((e >> 1) << 3);
                const int c = (ci << 7) + wc * 32 + nt * 8 + ((lane & 3) << 1) + (e & 1);
                sS[r * SS_STR + c] = sacc[nt][e] * 0.125f;
            }
        }
    }
    __syncthreads();

    // ---- softmax over the band; zero out-of-band inside window ----
#pragma unroll
    for (int rr = 0; rr < 4; rr++) {
        const int row = warp * 4 + rr;
        const int qi  = q0 + row;
        const int c0  = max(0, qi - RAD) - klo;
        const int c1  = min(SEQ - 1, qi + RAD) - klo;   // inclusive
        float mx = -1e30f;
        for (int c = c0 + lane; c <= c1; c += 32) mx = fmaxf(mx, sS[row * SS_STR + c]);
#pragma unroll
        for (int o = 16; o; o >>= 1) mx = fmaxf(mx, __shfl_xor_sync(0xffffffffu, mx, o));
        float sum = 0.f;
        for (int c = c0 + lane; c <= c1; c += 32) {
            const float e = __expf(sS[row * SS_STR + c] - mx);
            sS[row * SS_STR + c] = e;
            sum += e;
        }
#pragma unroll
        for (int o = 16; o; o >>= 1) sum += __shfl_xor_sync(0xffffffffu, sum, o);
        const float inv = 1.f / sum;
        for (int c = c0 + lane; c <= c1; c += 32) sS[row * SS_STR + c] *= inv;
        for (int c = lane; c < c0; c += 32) sS[row * SS_STR + c] = 0.f;
        for (int c = c1 + 1 + lane; c < Wd; c += 32) sS[row * SS_STR + c] = 0.f;
    }

    // ---- write p_attn window slice ----
    {
        float* Pg = p_out + ((size_t)bh * SEQ + q0) * SEQ + klo;
        const int Wd4 = Wd >> 2;
#pragma unroll
        for (int rr = 0; rr < 4; rr++) {
            const int row = warp * 4 + rr;
            for (int c4 = lane; c4 < Wd4; c4 += 32) {
                __stcs((float4*)&Pg[(size_t)row * SEQ + (c4 << 2)],
                       *(float4*)&sS[row * SS_STR + (c4 << 2)]);
            }
        }
    }

    // ---- O = P @ V (64 x 64), V streamed in chunks into sKV ----
    float oacc[2][4];
#pragma unroll
    for (int j = 0; j < 2; j++)
#pragma unroll
        for (int e = 0; e < 4; e++) oacc[j][e] = 0.f;

    for (int ci = 0; ci < nch; ci++) {
        const int ck0 = klo + (ci << 7);
        const int cw  = min(128, khi - ck0);
        __syncthreads();
        {
            const int r = tid >> 4, c = (tid & 15) << 2;
#pragma unroll
            for (int i = 0; i < 4; i++) {
                const int rr = r + (i << 5);
                float4 v = make_float4(0.f, 0.f, 0.f, 0.f);
                if (rr < cw) v = *(const float4*)&Vg[(size_t)(ck0 + rr) * DK + c];
                uint4 u;
                u.x = f2tf32(v.x); u.y = f2tf32(v.y); u.z = f2tf32(v.z); u.w = f2tf32(v.w);
                *(uint4*)&sKV[rr * SKV_STR + c] = u;
            }
        }
        __syncthreads();

#pragma unroll
        for (int kk = 0; kk < 128; kk += 8) {
            uint32_t af[4], bf[2][2];
            {
                const int r = wr * 16 + (lane >> 2);
                const int c = (ci << 7) + kk + (lane & 3);
                af[0] = f2tf32(sS[r * SS_STR + c]);
                af[1] = f2tf32(sS[(r + 8) * SS_STR + c]);
                af[2] = f2tf32(sS[r * SS_STR + c + 4]);
                af[3] = f2tf32(sS[(r + 8) * SS_STR + c + 4]);
            }
#pragma unroll
            for (int nt = 0; nt < 2; nt++) {
                const int n  = wc * 16 + nt * 8 + (lane >> 2);
                const int kd = kk + (lane & 3);
                bf[nt][0] = sKV[kd * SKV_STR + n];
                bf[nt][1] = sKV[(kd + 4) * SKV_STR + n];
            }
#pragma unroll
            for (int nt = 0; nt < 2; nt++) mma8(oacc[nt], af, bf[nt]);
        }
    }

    // ---- write X in [B,S,D] (head-concat) layout ----
    {
        const int b = bh >> 4, h = bh & 15;
#pragma unroll
        for (int nt = 0; nt < 2; nt++) {
#pragma unroll
            for (int e = 0; e < 4; e++) {
                const int r = wr * 16 + (lane >> 2) + ((e >> 1) << 3);
                const int c = wc * 16 + nt * 8 + ((lane & 3) << 1) + (e & 1);
                g_x[((size_t)b * SEQ + q0 + r) * DM + (h << 6) + c] = oacc[nt][e];
            }
        }
    }
}

// ======================================================================
// Launch
// ======================================================================
extern "C" void kernel_launch(void* const* d_in, const int* in_sizes, int n_in,
                              void* d_out, int out_size) {
    const float* query = (const float*)d_in[0];
    const float* key_  = (const float*)d_in[1];
    const float* value = (const float*)d_in[2];
    const float* Wq = (const float*)d_in[3];
    const float* bq = (const float*)d_in[4];
    const float* Wk = (const float*)d_in[5];
    const float* bk = (const float*)d_in[6];
    const float* Wv = (const float*)d_in[7];
    const float* bv = (const float*)d_in[8];
    const float* Wo = (const float*)d_in[9];
    const float* bo = (const float*)d_in[10];

    float* out = (float*)d_out;
    float* p   = out + (size_t)NBATCH * SEQ * DM;

    float *qp, *kp, *vp, *xp;
    cudaGetSymbolAddress((void**)&qp, g_q);
    cudaGetSymbolAddress((void**)&kp, g_k);
    cudaGetSymbolAddress((void**)&vp, g_v);
    cudaGetSymbolAddress((void**)&xp, g_x);

    cudaFuncSetAttribute((const void*)attn_kernel,
                         cudaFuncAttributeMaxDynamicSharedMemorySize, SMEM_ATT);
    cudaFuncSetAttribute((const void*)gemm_qkv_zero,
                         cudaFuncAttributeMaxDynamicSharedMemorySize, SMEM_GEMM);
    cudaFuncSetAttribute((const void*)gemm_out,
                         cudaFuncAttributeMaxDynamicSharedMemorySize, SMEM_GEMM);

    // z=0: zero-fill of p outside attention windows (overlapped with the
    // tensor-bound projection GEMMs); z=1..3: Q/K/V projections.
    gemm_qkv_zero<<<dim3(DM / 128, NROW / 128, 4), 256, SMEM_GEMM>>>(
        query, key_, value, Wq, Wk, Wv, bq, bk, bv, qp, kp, vp, (float4*)p);

    attn_kernel<<<dim3(SEQ / 64, NBATCH * NH), 512, SMEM_ATT>>>(p);

    gemm_out<<<dim3(DM / 128, NROW / 128), 256, SMEM_GEMM>>>(xp, Wo, bo, out);
}

// round 13
// speedup vs baseline: 1.3113x; 1.1829x over previous
#include <cuda_runtime.h>
#include <cuda_fp16.h>
#include <cstdint>
#include <math.h>

#define DI __device__ __forceinline__

constexpr int SEQ = 2048;
constexpr int DM  = 1024;
constexpr int NH  = 16;
constexpr int DK  = 64;
constexpr int RAD = 128;          // masksize // 2
constexpr int NBATCH = 2;
constexpr int NROW = NBATCH * SEQ;   // 4096 rows for all projections
constexpr int NZCTA = 512;           // zero-fill worker CTAs (z=0 and z=4 planes)

// ---------------- scratch (no allocation allowed) ----------------
__device__ __align__(256) float g_q[NBATCH * NH * SEQ * DK];
__device__ __align__(256) float g_k[NBATCH * NH * SEQ * DK];
__device__ __align__(256) float g_v[NBATCH * NH * SEQ * DK];
__device__ __align__(256) float g_x[NBATCH * SEQ * DM];

// ---------------- helpers ----------------
DI uint32_t f2tf32(float x) {
    uint32_t r;
    asm("cvt.rna.tf32.f32 %0, %1;" : "=r"(r) : "f"(x));
    return r;
}

// tf32 m16n8k8 (attention kernel)
DI void mma8(float* d, const uint32_t* a, const uint32_t* b) {
    asm volatile(
        "mma.sync.aligned.m16n8k8.row.col.f32.tf32.tf32.f32 "
        "{%0,%1,%2,%3}, {%4,%5,%6,%7}, {%8,%9}, {%0,%1,%2,%3};\n"
        : "+f"(d[0]), "+f"(d[1]), "+f"(d[2]), "+f"(d[3])
        : "r"(a[0]), "r"(a[1]), "r"(a[2]), "r"(a[3]),
          "r"(b[0]), "r"(b[1]));
}

// fp16 m16n8k16 (projection GEMMs)
DI void mma16(float* d, const uint32_t* a, const uint32_t* b) {
    asm volatile(
        "mma.sync.aligned.m16n8k16.row.col.f32.f16.f16.f32 "
        "{%0,%1,%2,%3}, {%4,%5,%6,%7}, {%8,%9}, {%0,%1,%2,%3};\n"
        : "+f"(d[0]), "+f"(d[1]), "+f"(d[2]), "+f"(d[3])
        : "r"(a[0]), "r"(a[1]), "r"(a[2]), "r"(a[3]),
          "r"(b[0]), "r"(b[1]));
}

DI uint32_t smem_u32(const void* p) {
    return (uint32_t)__cvta_generic_to_shared(p);
}
DI void ldsm4(uint32_t* r, uint32_t addr) {
    asm volatile("ldmatrix.sync.aligned.m8n8.x4.shared.b16 {%0,%1,%2,%3}, [%4];"
                 : "=r"(r[0]), "=r"(r[1]), "=r"(r[2]), "=r"(r[3]) : "r"(addr));
}
DI void ldsm4t(uint32_t* r, uint32_t addr) {
    asm volatile("ldmatrix.sync.aligned.m8n8.x4.trans.shared.b16 {%0,%1,%2,%3}, [%4];"
                 : "=r"(r[0]), "=r"(r[1]), "=r"(r[2]), "=r"(r[3]) : "r"(addr));
}

// ---------------- zero-fill body (p outside the attention windows) -----
DI void zero_p_body(float4* __restrict__ p, int cta, int ncta) {
    const size_t total = (size_t)32 * SEQ * (SEQ / 4);   // 33.5M float4
    const float4 z = make_float4(0.f, 0.f, 0.f, 0.f);
    const size_t stride = (size_t)ncta * 256;
    for (size_t i = (size_t)cta * 256 + threadIdx.x; i < total; i += stride) {
        const int col = ((int)(i & 511)) << 2;          // 0..2044 step 4
        const int row = (int)((i >> 9) & (SEQ - 1));
        const int q0  = row & ~63;
        const int klo = max(0, q0 - RAD);
        const int khi = min(SEQ, q0 + 64 + RAD);
        if (col >= klo && col < khi) continue;          // attn writes the window
        __stcs(&p[i], z);
    }
}

// ======================================================================
// GEMM body: out = X[4096,1024] @ W[1024,1024] + bias   (fp16 core)
// BM=128, BN=128, BK=32, 256 threads (8 warps as 2x4), warp tile 64x32.
// fp16 staged smem (cvt once at staging); fragments via ldmatrix:
//   per 32-k tile: 2 kk-steps x (4 LDSM + 2 LDSM.T + 16 HMMA.k16).
// A stride 40 halves (80B: LDSM sector stride 5 -> conflict-free);
// B stride 136 halves (272B: sector stride 17 -> conflict-free).
// mode 0: out[r*1024 + c]; mode 1: head-scatter to [B,H,S,dk]
// ======================================================================
constexpr int HA_STR = 40;    // halves
constexpr int HB_STR = 136;   // halves

DI void gemm_body(const float* __restrict__ X, const float* __restrict__ Wt,
                  const float* __restrict__ bias, float* __restrict__ out,
                  int mode, int bx, int by) {
    __shared__ __half As[128 * HA_STR];   // 10240 B
    __shared__ __half Bs[32 * HB_STR];    //  8704 B

    const int tid  = threadIdx.x;
    const int lane = tid & 31;
    const int warp = tid >> 5;
    const int row0 = by * 128;
    const int col0 = bx * 128;
    const int wm = (warp >> 2) * 64;   // 0 or 64
    const int wn = (warp & 3) * 32;    // 0..96

    float acc[4][4][4];
#pragma unroll
    for (int i = 0; i < 4; i++)
#pragma unroll
        for (int j = 0; j < 4; j++)
#pragma unroll
            for (int e = 0; e < 4; e++) acc[i][j][e] = 0.f;

    const int ar = tid >> 3,  ac = (tid & 7) << 2;    // A: 32 rows/pass x 32 cols
    const int br = tid >> 5,  bc = (tid & 31) << 2;   // B: 8 rows/pass x 128 cols

    for (int kt = 0; kt < DM; kt += 32) {
#pragma unroll
        for (int i = 0; i < 4; i++) {
            const float4 v = *(const float4*)&X[(size_t)(row0 + ar + 32 * i) * DM + kt + ac];
            __half* d = &As[(ar + 32 * i) * HA_STR + ac];
            *(__half2*)(d)     = __floats2half2_rn(v.x, v.y);
            *(__half2*)(d + 2) = __floats2half2_rn(v.z, v.w);
        }
#pragma unroll
        for (int i = 0; i < 4; i++) {
            const float4 v = *(const float4*)&Wt[(size_t)(kt + br + 8 * i) * DM + col0 + bc];
            __half* d = &Bs[(br + 8 * i) * HB_STR + bc];
            *(__half2*)(d)     = __floats2half2_rn(v.x, v.y);
            *(__half2*)(d + 2) = __floats2half2_rn(v.z, v.w);
        }
        __syncthreads();

#pragma unroll
        for (int k0 = 0; k0 < 32; k0 += 16) {
            uint32_t a[4][4], b[2][4];
            // A fragments: m16 tiles at wm + mt*16, k halves k0 / k0+8
#pragma unroll
            for (int mt = 0; mt < 4; mt++) {
                const int r = wm + mt * 16 + (lane & 15);
                const int c = k0 + ((lane >> 4) << 3);
                ldsm4(a[mt], smem_u32(&As[r * HA_STR + c]));
            }
            // B fragments (trans): n16 groups at wn + nb*16
#pragma unroll
            for (int nb = 0; nb < 2; nb++) {
                const int r = k0 + (lane & 15);
                const int c = wn + nb * 16 + ((lane >> 4) << 3);
                ldsm4t(b[nb], smem_u32(&Bs[r * HB_STR + c]));
            }
#pragma unroll
            for (int mt = 0; mt < 4; mt++)
#pragma unroll
                for (int nt = 0; nt < 4; nt++)
                    mma16(acc[mt][nt], a[mt], &b[nt >> 1][(nt & 1) * 2]);
        }
        __syncthreads();
    }

    // epilogue (c-frag layout identical to k8 variant)
#pragma unroll
    for (int mt = 0; mt < 4; mt++)
#pragma unroll
        for (int nt = 0; nt < 4; nt++) {
            const int r0 = row0 + wm + mt * 16 + (lane >> 2);
            const int c0 = col0 + wn + nt * 8 + ((lane & 3) << 1);
#pragma unroll
            for (int e = 0; e < 4; e++) {
                const int r = r0 + ((e >> 1) << 3);
                const int c = c0 + (e & 1);
                const float v = acc[mt][nt][e] + bias[c];
                if (mode == 0) {
                    out[(size_t)r * DM + c] = v;
                } else {
                    const int b2 = r >> 11, s2 = r & (SEQ - 1);
                    const int h = c >> 6,  d = c & 63;
                    out[((((size_t)b2 * NH + h) * SEQ + s2) << 6) + d] = v;
                }
            }
        }
}

// Fused launch: z=0 (early) and z=4 (late) -> zero-fill workers; z=1..3 ->
// Q/K/V projections. Early zeros overlap the gemms; late zeros finish with
// the whole chip's DRAM after tensor work drains.
__global__ __launch_bounds__(256, 2)
void gemm_qkv_zero(const float* __restrict__ xq, const float* __restrict__ xk,
                   const float* __restrict__ xv,
                   const float* __restrict__ wq, const float* __restrict__ wk,
                   const float* __restrict__ wv,
                   const float* __restrict__ bq, const float* __restrict__ bk,
                   const float* __restrict__ bv,
                   float* __restrict__ dq, float* __restrict__ dk,
                   float* __restrict__ dv, float4* __restrict__ p) {
    const int z = blockIdx.z;
    if (z == 0 || z == 4) {
        const int cta = blockIdx.y * gridDim.x + blockIdx.x + (z == 4 ? 256 : 0);
        zero_p_body(p, cta, NZCTA);
        return;
    }
    const float* X = (z == 1) ? xq : (z == 2) ? xk : xv;
    const float* W = (z == 1) ? wq : (z == 2) ? wk : wv;
    const float* b = (z == 1) ? bq : (z == 2) ? bk : bv;
    float*       d = (z == 1) ? dq : (z == 2) ? dk : dv;
    gemm_body(X, W, b, d, 1, blockIdx.x, blockIdx.y);
}

__global__ __launch_bounds__(256, 2)
void gemm_out(const float* __restrict__ X, const float* __restrict__ Wt,
              const float* __restrict__ bias, float* __restrict__ out) {
    gemm_body(X, Wt, bias, out, 0, blockIdx.x, blockIdx.y);
}

// ======================================================================
// Banded attention: one CTA = 64 queries x one (b,h). 512 threads.
// (unchanged — measured good)
// ======================================================================
constexpr int SQ_STR  = 68;
constexpr int SKV_STR = 76;
constexpr int SS_STR  = 388;
constexpr int SMEM_ATT = (64 * SQ_STR + 128 * SKV_STR + 64 * SS_STR) * 4;

__global__ __launch_bounds__(512)
void attn_kernel(float* __restrict__ p_out) {
    extern __shared__ char smraw[];
    uint32_t* sQ  = (uint32_t*)smraw;
    uint32_t* sKV = sQ + 64 * SQ_STR;
    float*    sS  = (float*)(sKV + 128 * SKV_STR);

    const int tid  = threadIdx.x;
    const int lane = tid & 31;
    const int warp = tid >> 5;           // 0..15
    const int bh = blockIdx.y;
    const int q0 = blockIdx.x * 64;
    const int klo = max(0, q0 - RAD);
    const int khi = min(SEQ, q0 + 64 + RAD);
    const int Wd  = khi - klo;
    const int nch = (Wd + 127) >> 7;

    const float* Qg = g_q + ((size_t)bh * SEQ + q0) * DK;
    const float* Kg = g_k + (size_t)bh * SEQ * DK;
    const float* Vg = g_v + (size_t)bh * SEQ * DK;

    // load Q (64 x 64), cvt to tf32 bits
    {
        const int r = tid >> 4, c = (tid & 15) << 2;
#pragma unroll
        for (int i = 0; i < 2; i++) {
            const float4 v = *(const float4*)&Qg[(size_t)(r + 32 * i) * DK + c];
            uint4 u;
            u.x = f2tf32(v.x); u.y = f2tf32(v.y); u.z = f2tf32(v.z); u.w = f2tf32(v.w);
            *(uint4*)&sQ[(r + 32 * i) * SQ_STR + c] = u;
        }
    }

    const int wr = warp >> 2;   // 0..3 : row group (16 rows)
    const int wc = warp & 3;    // 0..3 : col group

    // ---- scores: S = (Q @ K^T) * (1/8) into sS ----
    for (int ci = 0; ci < nch; ci++) {
        const int ck0 = klo + (ci << 7);
        const int cw  = min(128, khi - ck0);
        __syncthreads();
        {
            const int r = tid >> 4, c = (tid & 15) << 2;
#pragma unroll
            for (int i = 0; i < 4; i++) {
                const int rr = r + (i << 5);
                float4 v = make_float4(0.f, 0.f, 0.f, 0.f);
                if (rr < cw) v = *(const float4*)&Kg[(size_t)(ck0 + rr) * DK + c];
                uint4 u;
                u.x = f2tf32(v.x); u.y = f2tf32(v.y); u.z = f2tf32(v.z); u.w = f2tf32(v.w);
                *(uint4*)&sKV[rr * SKV_STR + c] = u;
            }
        }
        __syncthreads();

        float sacc[4][4];
#pragma unroll
        for (int j = 0; j < 4; j++)
#pragma unroll
            for (int e = 0; e < 4; e++) sacc[j][e] = 0.f;

#pragma unroll
        for (int kk = 0; kk < 64; kk += 8) {
            uint32_t af[4], bf[4][2];
            {
                const int r = wr * 16 + (lane >> 2);
                const int c = kk + (lane & 3);
                af[0] = sQ[r * SQ_STR + c];
                af[1] = sQ[(r + 8) * SQ_STR + c];
                af[2] = sQ[r * SQ_STR + c + 4];
                af[3] = sQ[(r + 8) * SQ_STR + c + 4];
            }
#pragma unroll
            for (int nt = 0; nt < 4; nt++) {
                const int key = wc * 32 + nt * 8 + (lane >> 2);
                const int kd  = kk + (lane & 3);
                bf[nt][0] = sKV[key * SKV_STR + kd];
                bf[nt][1] = sKV[key * SKV_STR + kd + 4];
            }
#pragma unroll
            for (int nt = 0; nt < 4; nt++) mma8(sacc[nt], af, bf[nt]);
        }
#pragma unroll
        for (int nt = 0; nt < 4; nt++) {
#pragma unroll
            for (int e = 0; e < 4; e++) {
                const int r = wr * 16 + (lane >> 2) + ((e >> 1) << 3);
                const int c = (ci << 7) + wc * 32 + nt * 8 + ((lane & 3) << 1) + (e & 1);
                sS[r * SS_STR + c] = sacc[nt][e] * 0.125f;
            }
        }
    }
    __syncthreads();

    // ---- softmax over the band; zero out-of-band inside window ----
#pragma unroll
    for (int rr = 0; rr < 4; rr++) {
        const int row = warp * 4 + rr;
        const int qi  = q0 + row;
        const int c0  = max(0, qi - RAD) - klo;
        const int c1  = min(SEQ - 1, qi + RAD) - klo;   // inclusive
        float mx = -1e30f;
        for (int c = c0 + lane; c <= c1; c += 32) mx = fmaxf(mx, sS[row * SS_STR + c]);
#pragma unroll
        for (int o = 16; o; o >>= 1) mx = fmaxf(mx, __shfl_xor_sync(0xffffffffu, mx, o));
        float sum = 0.f;
        for (int c = c0 + lane; c <= c1; c += 32) {
            const float e = __expf(sS[row * SS_STR + c] - mx);
            sS[row * SS_STR + c] = e;
            sum += e;
        }
#pragma unroll
        for (int o = 16; o; o >>= 1) sum += __shfl_xor_sync(0xffffffffu, sum, o);
        const float inv = 1.f / sum;
        for (int c = c0 + lane; c <= c1; c += 32) sS[row * SS_STR + c] *= inv;
        for (int c = lane; c < c0; c += 32) sS[row * SS_STR + c] = 0.f;
        for (int c = c1 + 1 + lane; c < Wd; c += 32) sS[row * SS_STR + c] = 0.f;
    }

    // ---- write p_attn window slice ----
    {
        float* Pg = p_out + ((size_t)bh * SEQ + q0) * SEQ + klo;
        const int Wd4 = Wd >> 2;
#pragma unroll
        for (int rr = 0; rr < 4; rr++) {
            const int row = warp * 4 + rr;
            for (int c4 = lane; c4 < Wd4; c4 += 32) {
                __stcs((float4*)&Pg[(size_t)row * SEQ + (c4 << 2)],
                       *(float4*)&sS[row * SS_STR + (c4 << 2)]);
            }
        }
    }

    // ---- O = P @ V (64 x 64), V streamed in chunks into sKV ----
    float oacc[2][4];
#pragma unroll
    for (int j = 0; j < 2; j++)
#pragma unroll
        for (int e = 0; e < 4; e++) oacc[j][e] = 0.f;

    for (int ci = 0; ci < nch; ci++) {
        const int ck0 = klo + (ci << 7);
        const int cw  = min(128, khi - ck0);
        __syncthreads();
        {
            const int r = tid >> 4, c = (tid & 15) << 2;
#pragma unroll
            for (int i = 0; i < 4; i++) {
                const int rr = r + (i << 5);
                float4 v = make_float4(0.f, 0.f, 0.f, 0.f);
                if (rr < cw) v = *(const float4*)&Vg[(size_t)(ck0 + rr) * DK + c];
                uint4 u;
                u.x = f2tf32(v.x); u.y = f2tf32(v.y); u.z = f2tf32(v.z); u.w = f2tf32(v.w);
                *(uint4*)&sKV[rr * SKV_STR + c] = u;
            }
        }
        __syncthreads();

#pragma unroll
        for (int kk = 0; kk < 128; kk += 8) {
            uint32_t af[4], bf[2][2];
            {
                const int r = wr * 16 + (lane >> 2);
                const int c = (ci << 7) + kk + (lane & 3);
                af[0] = f2tf32(sS[r * SS_STR + c]);
                af[1] = f2tf32(sS[(r + 8) * SS_STR + c]);
                af[2] = f2tf32(sS[r * SS_STR + c + 4]);
                af[3] = f2tf32(sS[(r + 8) * SS_STR + c + 4]);
            }
#pragma unroll
            for (int nt = 0; nt < 2; nt++) {
                const int n  = wc * 16 + nt * 8 + (lane >> 2);
                const int kd = kk + (lane & 3);
                bf[nt][0] = sKV[kd * SKV_STR + n];
                bf[nt][1] = sKV[(kd + 4) * SKV_STR + n];
            }
#pragma unroll
            for (int nt = 0; nt < 2; nt++) mma8(oacc[nt], af, bf[nt]);
        }
    }

    // ---- write X in [B,S,D] (head-concat) layout ----
    {
        const int b = bh >> 4, h = bh & 15;
#pragma unroll
        for (int nt = 0; nt < 2; nt++) {
#pragma unroll
            for (int e = 0; e < 4; e++) {
                const int r = wr * 16 + (lane >> 2) + ((e >> 1) << 3);
                const int c = wc * 16 + nt * 8 + ((lane & 3) << 1) + (e & 1);
                g_x[((size_t)b * SEQ + q0 + r) * DM + (h << 6) + c] = oacc[nt][e];
            }
        }
    }
}

// ======================================================================
// Launch
// ======================================================================
extern "C" void kernel_launch(void* const* d_in, const int* in_sizes, int n_in,
                              void* d_out, int out_size) {
    const float* query = (const float*)d_in[0];
    const float* key_  = (const float*)d_in[1];
    const float* value = (const float*)d_in[2];
    const float* Wq = (const float*)d_in[3];
    const float* bq = (const float*)d_in[4];
    const float* Wk = (const float*)d_in[5];
    const float* bk = (const float*)d_in[6];
    const float* Wv = (const float*)d_in[7];
    const float* bv = (const float*)d_in[8];
    const float* Wo = (const float*)d_in[9];
    const float* bo = (const float*)d_in[10];

    float* out = (float*)d_out;
    float* p   = out + (size_t)NBATCH * SEQ * DM;

    float *qp, *kp, *vp, *xp;
    cudaGetSymbolAddress((void**)&qp, g_q);
    cudaGetSymbolAddress((void**)&kp, g_k);
    cudaGetSymbolAddress((void**)&vp, g_v);
    cudaGetSymbolAddress((void**)&xp, g_x);

    cudaFuncSetAttribute((const void*)attn_kernel,
                         cudaFuncAttributeMaxDynamicSharedMemorySize, SMEM_ATT);

    // z=0 (early) + z=4 (late): zero-fill of p outside attention windows,
    // overlapped with / trailing the Q/K/V projections (z=1..3).
    gemm_qkv_zero<<<dim3(DM / 128, NROW / 128, 5), 256>>>(
        query, key_, value, Wq, Wk, Wv, bq, bk, bv, qp, kp, vp, (float4*)p);

    attn_kernel<<<dim3(SEQ / 64, NBATCH * NH), 512, SMEM_ATT>>>(p);

    gemm_out<<<dim3(DM / 128, NROW / 128), 256>>>(xp, Wo, bo, out);
}

// round 15
// speedup vs baseline: 1.4064x; 1.0726x over previous
#include <cuda_runtime.h>
#include <cuda_fp16.h>
#include <cstdint>
#include <math.h>

#define DI __device__ __forceinline__

constexpr int SEQ = 2048;
constexpr int DM  = 1024;
constexpr int NH  = 16;
constexpr int DK  = 64;
constexpr int RAD = 128;          // masksize // 2
constexpr int NBATCH = 2;
constexpr int NROW = NBATCH * SEQ;   // 4096 rows for all projections
constexpr int NZCTA = 512;           // zero-fill worker CTAs (z=0 and z=4 planes)

// ---------------- scratch (no allocation allowed) ----------------
__device__ __align__(256) float  g_q[NBATCH * NH * SEQ * DK];
__device__ __align__(256) float  g_k[NBATCH * NH * SEQ * DK];
__device__ __align__(256) float  g_v[NBATCH * NH * SEQ * DK];
__device__ __align__(256) __half g_xh[NROW * DM];          // attn output, fp16
__device__ __align__(256) __half g_hq[NROW * DM];          // fp16 inputs
__device__ __align__(256) __half g_hk[NROW * DM];
__device__ __align__(256) __half g_hv[NROW * DM];
__device__ __align__(256) __half g_hwq[DM * DM];           // fp16 weights
__device__ __align__(256) __half g_hwk[DM * DM];
__device__ __align__(256) __half g_hwv[DM * DM];
__device__ __align__(256) __half g_hwo[DM * DM];

// ---------------- helpers ----------------
DI uint32_t f2tf32(float x) {
    uint32_t r;
    asm("cvt.rna.tf32.f32 %0, %1;" : "=r"(r) : "f"(x));
    return r;
}

// tf32 m16n8k8 (attention kernel)
DI void mma8(float* d, const uint32_t* a, const uint32_t* b) {
    asm volatile(
        "mma.sync.aligned.m16n8k8.row.col.f32.tf32.tf32.f32 "
        "{%0,%1,%2,%3}, {%4,%5,%6,%7}, {%8,%9}, {%0,%1,%2,%3};\n"
        : "+f"(d[0]), "+f"(d[1]), "+f"(d[2]), "+f"(d[3])
        : "r"(a[0]), "r"(a[1]), "r"(a[2]), "r"(a[3]),
          "r"(b[0]), "r"(b[1]));
}

// fp16 m16n8k16 (projection GEMMs)
DI void mma16(float* d, const uint32_t* a, const uint32_t* b) {
    asm volatile(
        "mma.sync.aligned.m16n8k16.row.col.f32.f16.f16.f32 "
        "{%0,%1,%2,%3}, {%4,%5,%6,%7}, {%8,%9}, {%0,%1,%2,%3};\n"
        : "+f"(d[0]), "+f"(d[1]), "+f"(d[2]), "+f"(d[3])
        : "r"(a[0]), "r"(a[1]), "r"(a[2]), "r"(a[3]),
          "r"(b[0]), "r"(b[1]));
}

DI uint32_t smem_u32(const void* p) {
    return (uint32_t)__cvta_generic_to_shared(p);
}
DI void ldsm4(uint32_t* r, uint32_t addr) {
    asm volatile("ldmatrix.sync.aligned.m8n8.x4.shared.b16 {%0,%1,%2,%3}, [%4];"
                 : "=r"(r[0]), "=r"(r[1]), "=r"(r[2]), "=r"(r[3]) : "r"(addr));
}
DI void ldsm4t(uint32_t* r, uint32_t addr) {
    asm volatile("ldmatrix.sync.aligned.m8n8.x4.trans.shared.b16 {%0,%1,%2,%3}, [%4];"
                 : "=r"(r[0]), "=r"(r[1]), "=r"(r[2]), "=r"(r[3]) : "r"(addr));
}
DI void cp16(uint32_t dst, const void* src) {
    asm volatile("cp.async.cg.shared.global [%0], [%1], 16;\n" :: "r"(dst), "l"(src));
}
DI void cp_commit() { asm volatile("cp.async.commit_group;\n" ::: "memory"); }
DI void cp_wait0()  { asm volatile("cp.async.wait_group 0;\n" ::: "memory"); }

// ======================================================================
// fp32 -> fp16 pre-convert: z selects tensor (0..2 inputs, 3..6 weights)
// ======================================================================
__global__ __launch_bounds__(256)
void cvt_fp16(const float* __restrict__ xq, const float* __restrict__ xk,
              const float* __restrict__ xv,
              const float* __restrict__ wq, const float* __restrict__ wk,
              const float* __restrict__ wv, const float* __restrict__ wo,
              __half* __restrict__ dxq, __half* __restrict__ dxk,
              __half* __restrict__ dxv, __half* __restrict__ dwq,
              __half* __restrict__ dwk, __half* __restrict__ dwv,
              __half* __restrict__ dwo) {
    const int z = blockIdx.z;
    const float* s; __half* d; int n;
    switch (z) {
        case 0: s = xq; d = dxq; n = NROW * DM; break;
        case 1: s = xk; d = dxk; n = NROW * DM; break;
        case 2: s = xv; d = dxv; n = NROW * DM; break;
        case 3: s = wq; d = dwq; n = DM * DM; break;
        case 4: s = wk; d = dwk; n = DM * DM; break;
        case 5: s = wv; d = dwv; n = DM * DM; break;
        default: s = wo; d = dwo; n = DM * DM; break;
    }
    const float4* s4 = (const float4*)s;
    uint2* d4 = (uint2*)d;
    const int n4 = n >> 2;
    for (int i = blockIdx.x * blockDim.x + threadIdx.x; i < n4;
         i += gridDim.x * blockDim.x) {
        const float4 v = s4[i];
        __half2 a = __floats2half2_rn(v.x, v.y);
        __half2 b = __floats2half2_rn(v.z, v.w);
        d4[i] = make_uint2(*(uint32_t*)&a, *(uint32_t*)&b);
    }
}

// ---------------- zero-fill body (p outside the attention windows) -----
DI void zero_p_body(float4* __restrict__ p, int cta, int ncta) {
    const size_t total = (size_t)32 * SEQ * (SEQ / 4);   // 33.5M float4
    const float4 z = make_float4(0.f, 0.f, 0.f, 0.f);
    const size_t stride = (size_t)ncta * 256;
    for (size_t i = (size_t)cta * 256 + threadIdx.x; i < total; i += stride) {
        const int col = ((int)(i & 511)) << 2;          // 0..2044 step 4
        const int row = (int)((i >> 9) & (SEQ - 1));
        const int q0  = row & ~63;
        const int klo = max(0, q0 - RAD);
        const int khi = min(SEQ, q0 + 64 + RAD);
        if (col >= klo && col < khi) continue;          // attn writes the window
        __stcs(&p[i], z);
    }
}

// ======================================================================
// GEMM body: out = X[4096,1024] @ W[1024,1024] + bias   (fp16 operands)
// cp.async 2-stage double buffer: wait0 -> sync -> issue kt+1 -> mma kt.
// BM=128, BN=128, BK=32, 256 threads (8 warps as 2x4), warp tile 64x32.
// Fragments via ldmatrix (A stride 40 halves, B stride 136 -> conflict-free).
// 2 stages x 18.9KB = 37.9KB static smem; 2 CTAs/SM.
// mode 0: out[r*1024 + c]; mode 1: head-scatter to [B,H,S,dk]
// ======================================================================
constexpr int HA_STR = 40;    // halves
constexpr int HB_STR = 136;   // halves

DI void stage_tile(const __half* __restrict__ X, const __half* __restrict__ Wt,
                   __half* __restrict__ Asd, __half* __restrict__ Bsd,
                   int row0, int col0, int k0, int tid) {
    const int ar = tid >> 1, ac = (tid & 1) << 4;     // 128 rows x 32 halves
    cp16(smem_u32(&Asd[ar * HA_STR + ac]),     &X[(size_t)(row0 + ar) * DM + k0 + ac]);
    cp16(smem_u32(&Asd[ar * HA_STR + ac + 8]), &X[(size_t)(row0 + ar) * DM + k0 + ac + 8]);
    const int br = tid >> 3, bc = (tid & 7) << 4;     // 32 rows x 128 halves
    cp16(smem_u32(&Bsd[br * HB_STR + bc]),     &Wt[(size_t)(k0 + br) * DM + col0 + bc]);
    cp16(smem_u32(&Bsd[br * HB_STR + bc + 8]), &Wt[(size_t)(k0 + br) * DM + col0 + bc + 8]);
    cp_commit();
}

DI void gemm_body(const __half* __restrict__ X, const __half* __restrict__ Wt,
                  const float* __restrict__ bias, float* __restrict__ out,
                  int mode, int bx, int by) {
    __shared__ __half As[2][128 * HA_STR];   // 2 x 10240 B
    __shared__ __half Bs[2][32 * HB_STR];    // 2 x  8704 B

    const int tid  = threadIdx.x;
    const int lane = tid & 31;
    const int warp = tid >> 5;
    const int row0 = by * 128;
    const int col0 = bx * 128;
    const int wm = (warp >> 2) * 64;   // 0 or 64
    const int wn = (warp & 3) * 32;    // 0..96

    float acc[4][4][4];
#pragma unroll
    for (int i = 0; i < 4; i++)
#pragma unroll
        for (int j = 0; j < 4; j++)
#pragma unroll
            for (int e = 0; e < 4; e++) acc[i][j][e] = 0.f;

    stage_tile(X, Wt, As[0], Bs[0], row0, col0, 0, tid);   // prologue

    for (int kt = 0; kt < 32; kt++) {
        cp_wait0();
        __syncthreads();   // tile kt visible; prior reads of the other stage done

        if (kt < 31)
            stage_tile(X, Wt, As[(kt + 1) & 1], Bs[(kt + 1) & 1],
                       row0, col0, (kt + 1) << 5, tid);

        const __half* Asb = As[kt & 1];
        const __half* Bsb = Bs[kt & 1];
#pragma unroll
        for (int k0 = 0; k0 < 32; k0 += 16) {
            uint32_t a[4][4], b[2][4];
#pragma unroll
            for (int mt = 0; mt < 4; mt++) {
                const int r = wm + mt * 16 + (lane & 15);
                const int c = k0 + ((lane >> 4) << 3);
                ldsm4(a[mt], smem_u32(&Asb[r * HA_STR + c]));
            }
#pragma unroll
            for (int nb = 0; nb < 2; nb++) {
                const int r = k0 + (lane & 15);
                const int c = wn + nb * 16 + ((lane >> 4) << 3);
                ldsm4t(b[nb], smem_u32(&Bsb[r * HB_STR + c]));
            }
#pragma unroll
            for (int mt = 0; mt < 4; mt++)
#pragma unroll
                for (int nt = 0; nt < 4; nt++)
                    mma16(acc[mt][nt], a[mt], &b[nt >> 1][(nt & 1) * 2]);
        }
    }

    // epilogue
#pragma unroll
    for (int mt = 0; mt < 4; mt++)
#pragma unroll
        for (int nt = 0; nt < 4; nt++) {
            const int r0 = row0 + wm + mt * 16 + (lane >> 2);
            const int c0 = col0 + wn + nt * 8 + ((lane & 3) << 1);
#pragma unroll
            for (int e = 0; e < 4; e++) {
                const int r = r0 + ((e >> 1) << 3);
                const int c = c0 + (e & 1);
                const float v = acc[mt][nt][e] + bias[c];
                if (mode == 0) {
                    out[(size_t)r * DM + c] = v;
                } else {
                    const int b2 = r >> 11, s2 = r & (SEQ - 1);
                    const int h = c >> 6,  d = c & 63;
                    out[((((size_t)b2 * NH + h) * SEQ + s2) << 6) + d] = v;
                }
            }
        }
}

// Fused launch: z=0 (early) and z=4 (late) -> zero-fill workers; z=1..3 ->
// Q/K/V projections (fp16 operands via pre-convert).
__global__ __launch_bounds__(256, 2)
void gemm_qkv_zero(const __half* __restrict__ xq, const __half* __restrict__ xk,
                   const __half* __restrict__ xv,
                   const __half* __restrict__ wq, const __half* __restrict__ wk,
                   const __half* __restrict__ wv,
                   const float* __restrict__ bq, const float* __restrict__ bk,
                   const float* __restrict__ bv,
                   float* __restrict__ dq, float* __restrict__ dk,
                   float* __restrict__ dv, float4* __restrict__ p) {
    const int z = blockIdx.z;
    if (z == 0 || z == 4) {
        const int cta = blockIdx.y * gridDim.x + blockIdx.x + (z == 4 ? 256 : 0);
        zero_p_body(p, cta, NZCTA);
        return;
    }
    const __half* X = (z == 1) ? xq : (z == 2) ? xk : xv;
    const __half* W = (z == 1) ? wq : (z == 2) ? wk : wv;
    const float*  b = (z == 1) ? bq : (z == 2) ? bk : bv;
    float*        d = (z == 1) ? dq : (z == 2) ? dk : dv;
    gemm_body(X, W, b, d, 1, blockIdx.x, blockIdx.y);
}

__global__ __launch_bounds__(256, 2)
void gemm_out(const __half* __restrict__ X, const __half* __restrict__ Wt,
              const float* __restrict__ bias, float* __restrict__ out) {
    gemm_body(X, Wt, bias, out, 0, blockIdx.x, blockIdx.y);
}

// ======================================================================
// Banded attention: one CTA = 64 queries x one (b,h). 512 threads.
// (unchanged except: X output written as fp16 into g_xh)
// ======================================================================
constexpr int SQ_STR  = 68;
constexpr int SKV_STR = 76;
constexpr int SS_STR  = 388;
constexpr int SMEM_ATT = (64 * SQ_STR + 128 * SKV_STR + 64 * SS_STR) * 4;

__global__ __launch_bounds__(512)
void attn_kernel(float* __restrict__ p_out) {
    extern __shared__ char smraw[];
    uint32_t* sQ  = (uint32_t*)smraw;
    uint32_t* sKV = sQ + 64 * SQ_STR;
    float*    sS  = (float*)(sKV + 128 * SKV_STR);

    const int tid  = threadIdx.x;
    const int lane = tid & 31;
    const int warp = tid >> 5;           // 0..15
    const int bh = blockIdx.y;
    const int q0 = blockIdx.x * 64;
    const int klo = max(0, q0 - RAD);
    const int khi = min(SEQ, q0 + 64 + RAD);
    const int Wd  = khi - klo;
    const int nch = (Wd + 127) >> 7;

    const float* Qg = g_q + ((size_t)bh * SEQ + q0) * DK;
    const float* Kg = g_k + (size_t)bh * SEQ * DK;
    const float* Vg = g_v + (size_t)bh * SEQ * DK;

    // load Q (64 x 64), cvt to tf32 bits
    {
        const int r = tid >> 4, c = (tid & 15) << 2;
#pragma unroll
        for (int i = 0; i < 2; i++) {
            const float4 v = *(const float4*)&Qg[(size_t)(r + 32 * i) * DK + c];
            uint4 u;
            u.x = f2tf32(v.x); u.y = f2tf32(v.y); u.z = f2tf32(v.z); u.w = f2tf32(v.w);
            *(uint4*)&sQ[(r + 32 * i) * SQ_STR + c] = u;
        }
    }

    const int wr = warp >> 2;   // 0..3 : row group (16 rows)
    const int wc = warp & 3;    // 0..3 : col group

    // ---- scores: S = (Q @ K^T) * (1/8) into sS ----
    for (int ci = 0; ci < nch; ci++) {
        const int ck0 = klo + (ci << 7);
        const int cw  = min(128, khi - ck0);
        __syncthreads();
        {
            const int r = tid >> 4, c = (tid & 15) << 2;
#pragma unroll
            for (int i = 0; i < 4; i++) {
                const int rr = r + (i << 5);
                float4 v = make_float4(0.f, 0.f, 0.f, 0.f);
                if (rr < cw) v = *(const float4*)&Kg[(size_t)(ck0 + rr) * DK + c];
                uint4 u;
                u.x = f2tf32(v.x); u.y = f2tf32(v.y); u.z = f2tf32(v.z); u.w = f2tf32(v.w);
                *(uint4*)&sKV[rr * SKV_STR + c] = u;
            }
        }
        __syncthreads();

        float sacc[4][4];
#pragma unroll
        for (int j = 0; j < 4; j++)
#pragma unroll
            for (int e = 0; e < 4; e++) sacc[j][e] = 0.f;

#pragma unroll
        for (int kk = 0; kk < 64; kk += 8) {
            uint32_t af[4], bf[4][2];
            {
                const int r = wr * 16 + (lane >> 2);
                const int c = kk + (lane & 3);
                af[0] = sQ[r * SQ_STR + c];
                af[1] = sQ[(r + 8) * SQ_STR + c];
                af[2] = sQ[r * SQ_STR + c + 4];
                af[3] = sQ[(r + 8) * SQ_STR + c + 4];
            }
#pragma unroll
            for (int nt = 0; nt < 4; nt++) {
                const int key = wc * 32 + nt * 8 + (lane >> 2);
                const int kd  = kk + (lane & 3);
                bf[nt][0] = sKV[key * SKV_STR + kd];
                bf[nt][1] = sKV[key * SKV_STR + kd + 4];
            }
#pragma unroll
            for (int nt = 0; nt < 4; nt++) mma8(sacc[nt], af, bf[nt]);
        }
#pragma unroll
        for (int nt = 0; nt < 4; nt++) {
#pragma unroll
            for (int e = 0; e < 4; e++) {
                const int r = wr * 16 + (lane >> 2) + ((e >> 1) << 3);
                const int c = (ci << 7) + wc * 32 + nt * 8 + ((lane & 3) << 1) + (e & 1);
                sS[r * SS_STR + c] = sacc[nt][e] * 0.125f;
            }
        }
    }
    __syncthreads();

    // ---- softmax over the band; zero out-of-band inside window ----
#pragma unroll
    for (int rr = 0; rr < 4; rr++) {
        const int row = warp * 4 + rr;
        const int qi  = q0 + row;
        const int c0  = max(0, qi - RAD) - klo;
        const int c1  = min(SEQ - 1, qi + RAD) - klo;   // inclusive
        float mx = -1e30f;
        for (int c = c0 + lane; c <= c1; c += 32) mx = fmaxf(mx, sS[row * SS_STR + c]);
#pragma unroll
        for (int o = 16; o; o >>= 1) mx = fmaxf(mx, __shfl_xor_sync(0xffffffffu, mx, o));
        float sum = 0.f;
        for (int c = c0 + lane; c <= c1; c += 32) {
            const float e = __expf(sS[row * SS_STR + c] - mx);
            sS[row * SS_STR + c] = e;
            sum += e;
        }
#pragma unroll
        for (int o = 16; o; o >>= 1) sum += __shfl_xor_sync(0xffffffffu, sum, o);
        const float inv = 1.f / sum;
        for (int c = c0 + lane; c <= c1; c += 32) sS[row * SS_STR + c] *= inv;
        for (int c = lane; c < c0; c += 32) sS[row * SS_STR + c] = 0.f;
        for (int c = c1 + 1 + lane; c < Wd; c += 32) sS[row * SS_STR + c] = 0.f;
    }

    // ---- write p_attn window slice ----
    {
        float* Pg = p_out + ((size_t)bh * SEQ + q0) * SEQ + klo;
        const int Wd4 = Wd >> 2;
#pragma unroll
        for (int rr = 0; rr < 4; rr++) {
            const int row = warp * 4 + rr;
            for (int c4 = lane; c4 < Wd4; c4 += 32) {
                __stcs((float4*)&Pg[(size_t)row * SEQ + (c4 << 2)],
                       *(float4*)&sS[row * SS_STR + (c4 << 2)]);
            }
        }
    }

    // ---- O = P @ V (64 x 64), V streamed in chunks into sKV ----
    float oacc[2][4];
#pragma unroll
    for (int j = 0; j < 2; j++)
#pragma unroll
        for (int e = 0; e < 4; e++) oacc[j][e] = 0.f;

    for (int ci = 0; ci < nch; ci++) {
        const int ck0 = klo + (ci << 7);
        const int cw  = min(128, khi - ck0);
        __syncthreads();
        {
            const int r = tid >> 4, c = (tid & 15) << 2;
#pragma unroll
            for (int i = 0; i < 4; i++) {
                const int rr = r + (i << 5);
                float4 v = make_float4(0.f, 0.f, 0.f, 0.f);
                if (rr < cw) v = *(const float4*)&Vg[(size_t)(ck0 + rr) * DK + c];
                uint4 u;
                u.x = f2tf32(v.x); u.y = f2tf32(v.y); u.z = f2tf32(v.z); u.w = f2tf32(v.w);
                *(uint4*)&sKV[rr * SKV_STR + c] = u;
            }
        }
        __syncthreads();

#pragma unroll
        for (int kk = 0; kk < 128; kk += 8) {
            uint32_t af[4], bf[2][2];
            {
                const int r = wr * 16 + (lane >> 2);
                const int c = (ci << 7) + kk + (lane & 3);
                af[0] = f2tf32(sS[r * SS_STR + c]);
                af[1] = f2tf32(sS[(r + 8) * SS_STR + c]);
                af[2] = f2tf32(sS[r * SS_STR + c + 4]);
                af[3] = f2tf32(sS[(r + 8) * SS_STR + c + 4]);
            }
#pragma unroll
            for (int nt = 0; nt < 2; nt++) {
                const int n  = wc * 16 + nt * 8 + (lane >> 2);
                const int kd = kk + (lane & 3);
                bf[nt][0] = sKV[kd * SKV_STR + n];
                bf[nt][1] = sKV[(kd + 4) * SKV_STR + n];
            }
#pragma unroll
            for (int nt = 0; nt < 2; nt++) mma8(oacc[nt], af, bf[nt]);
        }
    }

    // ---- write X as fp16 into g_xh ([B,S,D] head-concat layout) ----
    {
        const int b = bh >> 4, h = bh & 15;
        const int r0v = wr * 16 + (lane >> 2);
#pragma unroll
        for (int nt = 0; nt < 2; nt++) {
            const int c0v = wc * 16 + nt * 8 + ((lane & 3) << 1);
            *(__half2*)&g_xh[((size_t)b * SEQ + q0 + r0v) * DM + (h << 6) + c0v] =
                __floats2half2_rn(oacc[nt][0], oacc[nt][1]);
            *(__half2*)&g_xh[((size_t)b * SEQ + q0 + r0v + 8) * DM + (h << 6) + c0v] =
                __floats2half2_rn(oacc[nt][2], oacc[nt][3]);
        }
    }
}

// ======================================================================
// Launch
// ======================================================================
extern "C" void kernel_launch(void* const* d_in, const int* in_sizes, int n_in,
                              void* d_out, int out_size) {
    const float* query = (const float*)d_in[0];
    const float* key_  = (const float*)d_in[1];
    const float* value = (const float*)d_in[2];
    const float* Wq = (const float*)d_in[3];
    const float* bq = (const float*)d_in[4];
    const float* Wk = (const float*)d_in[5];
    const float* bk = (const float*)d_in[6];
    const float* Wv = (const float*)d_in[7];
    const float* bv = (const float*)d_in[8];
    const float* Wo = (const float*)d_in[9];
    const float* bo = (const float*)d_in[10];

    float* out = (float*)d_out;
    float* p   = out + (size_t)NBATCH * SEQ * DM;

    float *qp, *kp, *vp;
    __half *xh, *hq, *hk, *hv, *hwq, *hwk, *hwv, *hwo;
    cudaGetSymbolAddress((void**)&qp, g_q);
    cudaGetSymbolAddress((void**)&kp, g_k);
    cudaGetSymbolAddress((void**)&vp, g_v);
    cudaGetSymbolAddress((void**)&xh, g_xh);
    cudaGetSymbolAddress((void**)&hq, g_hq);
    cudaGetSymbolAddress((void**)&hk, g_hk);
    cudaGetSymbolAddress((void**)&hv, g_hv);
    cudaGetSymbolAddress((void**)&hwq, g_hwq);
    cudaGetSymbolAddress((void**)&hwk, g_hwk);
    cudaGetSymbolAddress((void**)&hwv, g_hwv);
    cudaGetSymbolAddress((void**)&hwo, g_hwo);

    cudaFuncSetAttribute((const void*)attn_kernel,
                         cudaFuncAttributeMaxDynamicSharedMemorySize, SMEM_ATT);

    // fp32 -> fp16 pre-convert of inputs and weights
    cvt_fp16<<<dim3(192, 1, 7), 256>>>(query, key_, value, Wq, Wk, Wv, Wo,
                                       hq, hk, hv, hwq, hwk, hwv, hwo);

    // z=0 (early) + z=4 (late): zero-fill of p outside attention windows;
    // z=1..3: Q/K/V projections (fp16 cp.async pipeline).
    gemm_qkv_zero<<<dim3(DM / 128, NROW / 128, 5), 256>>>(
        hq, hk, hv, hwq, hwk, hwv, bq, bk, bv, qp, kp, vp, (float4*)p);

    attn_kernel<<<dim3(SEQ / 64, NBATCH * NH), 512, SMEM_ATT>>>(p);

    gemm_out<<<dim3(DM / 128, NROW / 128), 256>>>(xh, hwo, bo, out);
}